// round 8
// baseline (speedup 1.0000x reference)
#include <cuda_runtime.h>
#include <cuda_bf16.h>
#include <cuda_fp16.h>
#include <math.h>
#include <stdint.h>

#define BD   2
#define SEQ  2048
#define DM   1024
#define NH   16
#define DH   64
#define MTOT (BD*SEQ)    // 4096
#define BHT  (BD*NH)     // 32

// Q pre-scale: 0.125 * log2(e) so scores arrive in log2 units
#define QSCALE 0.18033688011112042f
#define ONESH2 0x3C003C00u

// ---------------------------------------------------------------------------
// scratch (__device__ globals; allocation-free rule)
// ---------------------------------------------------------------------------
__device__ __half g_q  [BHT*SEQ*DH];     // RoPE'd Q (pre-scaled), fp16 [bh][s][d]
__device__ __half g_k  [BHT*SEQ*DH];     // RoPE'd K
__device__ __half g_v  [BHT*SEQ*DH];     // V
__device__ __half g_xh [MTOT*DM];        // x in fp16
__device__ __half g_wq [DM*DM], g_wk[DM*DM], g_wv[DM*DM], g_wo[DM*DM];
__device__ __half g_ohf[MTOT*DM];        // head outputs [token][dmodel] fp16
__device__ float  g_inv[BHT*SEQ];        // per-row 1/rowsum

// ---------------------------------------------------------------------------
// helpers
// ---------------------------------------------------------------------------
__device__ __forceinline__ uint32_t smem_u32(const void* p) {
    uint32_t a;
    asm("{ .reg .u64 t; cvta.to.shared.u64 t, %1; cvt.u32.u64 %0, t; }" : "=r"(a) : "l"(p));
    return a;
}
__device__ __forceinline__ void ldsm4(uint32_t r[4], uint32_t addr) {
    asm volatile("ldmatrix.sync.aligned.m8n8.x4.shared.b16 {%0,%1,%2,%3}, [%4];"
        : "=r"(r[0]), "=r"(r[1]), "=r"(r[2]), "=r"(r[3]) : "r"(addr));
}
__device__ __forceinline__ void ldsm4t(uint32_t r[4], uint32_t addr) {
    asm volatile("ldmatrix.sync.aligned.m8n8.x4.trans.shared.b16 {%0,%1,%2,%3}, [%4];"
        : "=r"(r[0]), "=r"(r[1]), "=r"(r[2]), "=r"(r[3]) : "r"(addr));
}
__device__ __forceinline__ void mmah(float* c, const uint32_t* a, uint32_t b0, uint32_t b1) {
    asm volatile("mma.sync.aligned.m16n8k16.row.col.f32.f16.f16.f32 "
        "{%0,%1,%2,%3}, {%4,%5,%6,%7}, {%8,%9}, {%0,%1,%2,%3};"
        : "+f"(c[0]), "+f"(c[1]), "+f"(c[2]), "+f"(c[3])
        : "r"(a[0]), "r"(a[1]), "r"(a[2]), "r"(a[3]), "r"(b0), "r"(b1));
}
__device__ __forceinline__ void cp16(uint32_t dst, const void* src) {
    asm volatile("cp.async.cg.shared.global [%0], [%1], 16;" :: "r"(dst), "l"(src));
}
#define CP_COMMIT() asm volatile("cp.async.commit_group;" ::: "memory")
#define CP_WAIT0()  asm volatile("cp.async.wait_group 0;" ::: "memory")
#define SW(o) ((o) ^ (((o) >> 3) & 0x70))

__device__ __forceinline__ uint32_t h2pack(float a, float b) {
    __half2 h = __floats2half2_rn(a, b);
    return *(uint32_t*)&h;
}
__device__ __forceinline__ uint32_t cvt_f16x2(float hi, float lo) {
    uint32_t d; asm("cvt.rn.f16x2.f32 %0, %1, %2;" : "=r"(d) : "f"(hi), "f"(lo)); return d;
}
__device__ __forceinline__ uint32_t ex2_f16x2(uint32_t a) {
    uint32_t d; asm("ex2.approx.f16x2 %0, %1;" : "=r"(d) : "r"(a)); return d;
}
__device__ __forceinline__ float ex2f(float a) {
    float d; asm("ex2.approx.f32 %0, %1;" : "=f"(d) : "f"(a)); return d;
}

// ---------------------------------------------------------------------------
// prep: fp32 -> fp16
// ---------------------------------------------------------------------------
__global__ __launch_bounds__(256) void tohalf_kernel(
    const float4* __restrict__ src, uint2* __restrict__ dst, int n4)
{
    int i = blockIdx.x * 256 + threadIdx.x;
    if (i >= n4) return;
    float4 v = src[i];
    uint2 o;
    o.x = h2pack(v.x, v.y);
    o.y = h2pack(v.z, v.w);
    dst[i] = o;
}

__global__ __launch_bounds__(256) void tohalf4_kernel(
    const float4* __restrict__ s0, const float4* __restrict__ s1,
    const float4* __restrict__ s2, const float4* __restrict__ s3,
    uint2* __restrict__ d0, uint2* __restrict__ d1,
    uint2* __restrict__ d2, uint2* __restrict__ d3, int n4)
{
    int y = blockIdx.y;
    const float4* s = (y==0) ? s0 : (y==1) ? s1 : (y==2) ? s2 : s3;
    uint2* d       = (y==0) ? d0 : (y==1) ? d1 : (y==2) ? d2 : d3;
    int i = blockIdx.x * 256 + threadIdx.x;
    if (i >= n4) return;
    float4 v = s[i];
    uint2 o;
    o.x = h2pack(v.x, v.y);
    o.y = h2pack(v.z, v.w);
    d[i] = o;
}

// ---------------------------------------------------------------------------
// GEMM core (fp16 HMMA, cp.async 2-stage): C(128x128) = A(128xK) @ B(KxN)
// ---------------------------------------------------------------------------
#define GQ_STG  32768
#define GQ_FREQ 65536
#define GQ_SMEM (GQ_FREQ + 128)

__device__ __forceinline__ void gemm_prefetch(
    uint32_t sb, int buf, int tid, int m0, int n0, int k0,
    const __half* A, int lda, const __half* B, int ldb)
{
    const uint32_t ab = sb + buf*GQ_STG;
    const uint32_t bb = ab + 16384;
    #pragma unroll
    for (int i = 0; i < 4; i++) {
        int c = tid + i*256;
        int row = c >> 3, part = c & 7;
        cp16(ab + SW((uint32_t)(row*128 + part*16)), A + (size_t)(m0+row)*lda + k0 + part*8);
    }
    #pragma unroll
    for (int i = 0; i < 4; i++) {
        int c = tid + i*256;
        int krow = c >> 4, chunk = c & 15;
        int half_ = chunk >> 3, nl = (chunk & 7) * 8;
        cp16(bb + (uint32_t)(half_*8192) + SW((uint32_t)(krow*128 + nl*2)),
             B + (size_t)(k0+krow)*ldb + n0 + chunk*8);
    }
}

__device__ __forceinline__ void gemm_tile_mma_h(
    uint32_t base, int lane, int wy, int wx, float acc[4][4][4])
{
    const uint32_t ba = base, bbb = base + 16384;
    const int g = lane >> 3;
    const int arow = wy*64 + (lane & 7) + ((lane >> 3) & 1) * 8;
    #pragma unroll
    for (int ks = 0; ks < 4; ks++) {
        uint32_t a[4][4];
        const uint32_t abase = (uint32_t)(arow*128 + ks*32 + (lane & 16));
        #pragma unroll
        for (int mt = 0; mt < 4; mt++)
            ldsm4(a[mt], ba + SW(abase + mt*16*128));
        #pragma unroll
        for (int np = 0; np < 2; np++) {
            const int krow = ks*16 + (g & 1)*8 + (lane & 7);
            const int nlg = wx*32 + np*16 + (g >> 1)*8;
            const uint32_t boff = (uint32_t)((nlg >> 6)*8192) + SW((uint32_t)(krow*128 + (nlg & 63)*2));
            uint32_t b[4];
            ldsm4t(b, bbb + boff);
            #pragma unroll
            for (int mt = 0; mt < 4; mt++) {
                mmah(acc[mt][np*2+0], a[mt], b[0], b[1]);
                mmah(acc[mt][np*2+1], a[mt], b[2], b[3]);
            }
        }
    }
}

// ---------------------------------------------------------------------------
// QKV projection; epilogue: +bias, RoPE (q,k), Q pre-scaled, store fp16
// ---------------------------------------------------------------------------
__global__ __launch_bounds__(256) void qkv_mma_kernel(
    const float* __restrict__ bq, const float* __restrict__ bk, const float* __restrict__ bv)
{
    extern __shared__ __align__(1024) char smem[];
    const uint32_t sb = smem_u32(smem);
    const int tid = threadIdx.x, wid = tid >> 5, lane = tid & 31;
    const int wy = wid >> 2, wx = wid & 3;
    const int n0 = blockIdx.x * 128;
    const int m0 = blockIdx.y * 128;
    const int z = blockIdx.z;

    const __half* B    = (z==0) ? g_wq : (z==1) ? g_wk : g_wv;
    const float* bias  = (z==0) ? bq   : (z==1) ? bk   : bv;

    float* s_freq = (float*)(smem + GQ_FREQ);
    if (tid < 32)
        s_freq[tid] = (float)(1.0 / pow(10000.0, (double)(2*tid) / 64.0));

    float acc[4][4][4];
    #pragma unroll
    for (int a = 0; a < 4; a++)
        #pragma unroll
        for (int b = 0; b < 4; b++)
            #pragma unroll
            for (int c = 0; c < 4; c++) acc[a][b][c] = 0.f;

    gemm_prefetch(sb, 0, tid, m0, n0, 0, g_xh, DM, B, DM);
    CP_COMMIT();
    for (int kt = 0; kt < 16; kt++) {
        CP_WAIT0();
        __syncthreads();
        if (kt < 15) {
            gemm_prefetch(sb, (kt+1) & 1, tid, m0, n0, (kt+1)*64, g_xh, DM, B, DM);
            CP_COMMIT();
        }
        gemm_tile_mma_h(sb + (kt & 1)*GQ_STG, lane, wy, wx, acc);
    }

    __half* dst = (z==0) ? g_q : (z==1) ? g_k : g_v;
    const int gr = lane >> 2, qc = (lane & 3) * 2;
    #pragma unroll
    for (int mt = 0; mt < 4; mt++) {
        #pragma unroll
        for (int h = 0; h < 2; h++) {
            int r = m0 + wy*64 + mt*16 + h*8 + gr;
            int bb = r >> 11;
            int s  = r & 2047;
            #pragma unroll
            for (int nt = 0; nt < 4; nt++) {
                int c = n0 + wx*32 + nt*8 + qc;   // even col
                float v0 = acc[mt][nt][h*2+0] + bias[c];
                float v1 = acc[mt][nt][h*2+1] + bias[c+1];
                float ox = v0, oy = v1;
                if (z < 2) {
                    float fr = s_freq[(c & 63) >> 1];
                    float sn, cs;
                    sincosf((float)s * fr, &sn, &cs);
                    ox = v0*cs - v1*sn;
                    oy = v0*sn + v1*cs;
                    if (z == 0) { ox *= QSCALE; oy *= QSCALE; }
                }
                int bh = bb*NH + (c >> 6);
                size_t idx = ((size_t)bh*SEQ + s)*DH + (c & 63);
                *(uint32_t*)(dst + idx) = h2pack(ox, oy);
            }
        }
    }
}

// ---------------------------------------------------------------------------
// Pass A: S=QK^T, P=ex2.f16x2(S), rowsum via ones-MMA, PV accumulate.
// Writes g_inv + head outputs. No attn writes.
// ---------------------------------------------------------------------------
#define FA_SQ   0
#define FA_K0   16384
#define FA_K1   24576
#define FA_V0   32768
#define FA_V1   40960
#define FA_SMEM 49152

__device__ __forceinline__ void fa_prefetch_kv(uint32_t sb, int buf, int bh, int k0, int tid)
{
    const __half* kp = g_k + ((size_t)bh*SEQ + k0)*DH;
    const __half* vp = g_v + ((size_t)bh*SEQ + k0)*DH;
    const uint32_t kb = sb + (buf ? FA_K1 : FA_K0);
    const uint32_t vb = sb + (buf ? FA_V1 : FA_V0);
    #pragma unroll
    for (int i = 0; i < 2; i++) {
        int c = tid + i*256;
        int row = c >> 3, part = c & 7;
        uint32_t off = SW((uint32_t)(row*128 + part*16));
        cp16(kb + off, kp + (size_t)row*DH + part*8);
        cp16(vb + off, vp + (size_t)row*DH + part*8);
    }
}

__global__ __launch_bounds__(256) void fattn_a_kernel()
{
    extern __shared__ __align__(1024) char smem[];
    const uint32_t sb = smem_u32(smem);
    const int tid = threadIdx.x, wid = tid >> 5, lane = tid & 31;
    const int m0 = blockIdx.x * 128;
    const int bh = blockIdx.y;
    const int g = lane >> 3, gr = lane >> 2, qc = (lane & 3) * 2;

    // load Q tile (128 x 64 fp16, swizzled)
    {
        const uint4* qsrc = (const uint4*)(g_q + ((size_t)bh*SEQ + m0)*DH);
        #pragma unroll
        for (int i = 0; i < 4; i++) {
            int c = tid + i*256;
            int row = c >> 3, part = c & 7;
            *(uint4*)(smem + FA_SQ + SW((uint32_t)(row*128 + part*16))) = qsrc[row*8 + part];
        }
    }
    fa_prefetch_kv(sb, 0, bh, 0, tid);
    CP_COMMIT();
    __syncthreads();

    uint32_t qf[4][4];
    {
        const int arow = wid*16 + (lane & 7) + ((lane >> 3) & 1)*8;
        #pragma unroll
        for (int ks = 0; ks < 4; ks++)
            ldsm4(qf[ks], sb + FA_SQ + SW((uint32_t)(arow*128 + ks*32 + (lane & 16))));
    }

    float o[8][4];
    #pragma unroll
    for (int t = 0; t < 8; t++)
        #pragma unroll
        for (int j = 0; j < 4; j++) o[t][j] = 0.f;
    float ors[4] = {0.f, 0.f, 0.f, 0.f};

    for (int kt = 0; kt < 32; kt++) {
        CP_WAIT0();
        __syncthreads();
        if (kt < 31) { fa_prefetch_kv(sb, (kt+1) & 1, bh, (kt+1)*64, tid); CP_COMMIT(); }

        const uint32_t kb = sb + ((kt & 1) ? FA_K1 : FA_K0);
        const uint32_t vb = sb + ((kt & 1) ? FA_V1 : FA_V0);

        float S[8][4];
        #pragma unroll
        for (int t = 0; t < 8; t++)
            #pragma unroll
            for (int j = 0; j < 4; j++) S[t][j] = 0.f;

        #pragma unroll
        for (int np = 0; np < 4; np++) {
            const int nrow = np*16 + (g >> 1)*8 + (lane & 7);
            #pragma unroll
            for (int ks = 0; ks < 4; ks++) {
                uint32_t bK[4];
                ldsm4(bK, kb + SW((uint32_t)(nrow*128 + ks*32 + (g & 1)*16)));
                mmah(S[np*2+0], qf[ks], bK[0], bK[1]);
                mmah(S[np*2+1], qf[ks], bK[2], bK[3]);
            }
        }

        uint32_t P01[8], P23[8];
        #pragma unroll
        for (int t = 0; t < 8; t++) {
            P01[t] = ex2_f16x2(cvt_f16x2(S[t][1], S[t][0]));
            P23[t] = ex2_f16x2(cvt_f16x2(S[t][3], S[t][2]));
        }

        #pragma unroll
        for (int kk = 0; kk < 4; kk++) {
            uint32_t aP[4];
            aP[0] = P01[2*kk];   aP[1] = P23[2*kk];
            aP[2] = P01[2*kk+1]; aP[3] = P23[2*kk+1];
            mmah(ors, aP, ONESH2, ONESH2);
            const int krow = kk*16 + (g & 1)*8 + (lane & 7);
            #pragma unroll
            for (int np = 0; np < 4; np++) {
                const int ncol = np*16 + (g >> 1)*8;
                uint32_t bV[4];
                ldsm4t(bV, vb + SW((uint32_t)(krow*128 + ncol*2)));
                mmah(o[np*2+0], aP, bV[0], bV[1]);
                mmah(o[np*2+1], aP, bV[2], bV[3]);
            }
        }
    }

    const float inv0 = 1.f / ors[0];
    const float inv1 = 1.f / ors[2];

    const int row0 = m0 + wid*16 + gr;
    if ((lane & 3) == 0) {
        g_inv[(size_t)bh*SEQ + row0]     = inv0;
        g_inv[(size_t)bh*SEQ + row0 + 8] = inv1;
    }

    const int bb = bh >> 4, hh = bh & 15;
    __half* o0 = g_ohf + ((size_t)bb*SEQ + row0)*DM + hh*64;
    __half* o1 = o0 + 8*DM;
    #pragma unroll
    for (int t = 0; t < 8; t++) {
        *(uint32_t*)(o0 + t*8 + qc) = h2pack(o[t][0]*inv0, o[t][1]*inv0);
        *(uint32_t*)(o1 + t*8 + qc) = h2pack(o[t][2]*inv1, o[t][3]*inv1);
    }
}

// ---------------------------------------------------------------------------
// Pass B: recompute S, write ex2f(S)*inv (normalized attn) once, streaming.
// Lower smem (32KB) / regs -> higher occupancy.
// ---------------------------------------------------------------------------
#define FB_SQ   0
#define FB_K0   16384
#define FB_K1   24576
#define FB_SMEM 32768

__device__ __forceinline__ void fb_prefetch_k(uint32_t sb, int buf, int bh, int k0, int tid)
{
    const __half* kp = g_k + ((size_t)bh*SEQ + k0)*DH;
    const uint32_t kb = sb + (buf ? FB_K1 : FB_K0);
    #pragma unroll
    for (int i = 0; i < 2; i++) {
        int c = tid + i*256;
        int row = c >> 3, part = c & 7;
        cp16(kb + SW((uint32_t)(row*128 + part*16)), kp + (size_t)row*DH + part*8);
    }
}

__global__ __launch_bounds__(256) void fattn_b_kernel(float* __restrict__ attn)
{
    extern __shared__ __align__(1024) char smem[];
    const uint32_t sb = smem_u32(smem);
    const int tid = threadIdx.x, wid = tid >> 5, lane = tid & 31;
    const int m0 = blockIdx.x * 128;
    const int bh = blockIdx.y;
    const int g = lane >> 3, gr = lane >> 2, qc = (lane & 3) * 2;

    {
        const uint4* qsrc = (const uint4*)(g_q + ((size_t)bh*SEQ + m0)*DH);
        #pragma unroll
        for (int i = 0; i < 4; i++) {
            int c = tid + i*256;
            int row = c >> 3, part = c & 7;
            *(uint4*)(smem + FB_SQ + SW((uint32_t)(row*128 + part*16))) = qsrc[row*8 + part];
        }
    }
    fb_prefetch_k(sb, 0, bh, 0, tid);
    CP_COMMIT();
    __syncthreads();

    uint32_t qf[4][4];
    {
        const int arow = wid*16 + (lane & 7) + ((lane >> 3) & 1)*8;
        #pragma unroll
        for (int ks = 0; ks < 4; ks++)
            ldsm4(qf[ks], sb + FB_SQ + SW((uint32_t)(arow*128 + ks*32 + (lane & 16))));
    }

    const int row0 = m0 + wid*16 + gr;
    const float inv0 = g_inv[(size_t)bh*SEQ + row0];
    const float inv1 = g_inv[(size_t)bh*SEQ + row0 + 8];
    float* arow0 = attn + ((size_t)bh*SEQ + row0)*SEQ;
    float* arow1 = arow0 + 8*SEQ;

    for (int kt = 0; kt < 32; kt++) {
        CP_WAIT0();
        __syncthreads();
        if (kt < 31) { fb_prefetch_k(sb, (kt+1) & 1, bh, (kt+1)*64, tid); CP_COMMIT(); }

        const uint32_t kb = sb + ((kt & 1) ? FB_K1 : FB_K0);

        float S[8][4];
        #pragma unroll
        for (int t = 0; t < 8; t++)
            #pragma unroll
            for (int j = 0; j < 4; j++) S[t][j] = 0.f;

        #pragma unroll
        for (int np = 0; np < 4; np++) {
            const int nrow = np*16 + (g >> 1)*8 + (lane & 7);
            #pragma unroll
            for (int ks = 0; ks < 4; ks++) {
                uint32_t bK[4];
                ldsm4(bK, kb + SW((uint32_t)(nrow*128 + ks*32 + (g & 1)*16)));
                mmah(S[np*2+0], qf[ks], bK[0], bK[1]);
                mmah(S[np*2+1], qf[ks], bK[2], bK[3]);
            }
        }

        #pragma unroll
        for (int t = 0; t < 8; t++) {
            float e0 = ex2f(S[t][0]) * inv0;
            float e1 = ex2f(S[t][1]) * inv0;
            float e2 = ex2f(S[t][2]) * inv1;
            float e3 = ex2f(S[t][3]) * inv1;
            int col = kt*64 + t*8 + qc;
            __stcs((float2*)(arow0 + col), make_float2(e0, e1));
            __stcs((float2*)(arow1 + col), make_float2(e2, e3));
        }
    }
}

// ---------------------------------------------------------------------------
// Output projection: out = oh @ Wo + bo
// ---------------------------------------------------------------------------
__global__ __launch_bounds__(256) void outproj_mma_kernel(
    const float* __restrict__ bo, float* __restrict__ out)
{
    extern __shared__ __align__(1024) char smem[];
    const uint32_t sb = smem_u32(smem);
    const int tid = threadIdx.x, wid = tid >> 5, lane = tid & 31;
    const int wy = wid >> 2, wx = wid & 3;
    const int n0 = blockIdx.x * 128;
    const int m0 = blockIdx.y * 128;

    float acc[4][4][4];
    #pragma unroll
    for (int a = 0; a < 4; a++)
        #pragma unroll
        for (int b = 0; b < 4; b++)
            #pragma unroll
            for (int c = 0; c < 4; c++) acc[a][b][c] = 0.f;

    gemm_prefetch(sb, 0, tid, m0, n0, 0, g_ohf, DM, g_wo, DM);
    CP_COMMIT();
    for (int kt = 0; kt < 16; kt++) {
        CP_WAIT0();
        __syncthreads();
        if (kt < 15) {
            gemm_prefetch(sb, (kt+1) & 1, tid, m0, n0, (kt+1)*64, g_ohf, DM, g_wo, DM);
            CP_COMMIT();
        }
        gemm_tile_mma_h(sb + (kt & 1)*GQ_STG, lane, wy, wx, acc);
    }

    const int gr = lane >> 2, qc = (lane & 3) * 2;
    #pragma unroll
    for (int mt = 0; mt < 4; mt++) {
        #pragma unroll
        for (int h = 0; h < 2; h++) {
            int r = m0 + wy*64 + mt*16 + h*8 + gr;
            #pragma unroll
            for (int nt = 0; nt < 4; nt++) {
                int c = n0 + wx*32 + nt*8 + qc;
                float2 oo;
                oo.x = acc[mt][nt][h*2+0] + bo[c];
                oo.y = acc[mt][nt][h*2+1] + bo[c+1];
                *(float2*)(out + (size_t)r*DM + c) = oo;
            }
        }
    }
}

// ---------------------------------------------------------------------------
extern "C" void kernel_launch(void* const* d_in, const int* in_sizes, int n_in,
                              void* d_out, int out_size)
{
    const float* x  = (const float*)d_in[0];
    const float* wq = (const float*)d_in[1];
    const float* bq = (const float*)d_in[2];
    const float* wk = (const float*)d_in[3];
    const float* bk = (const float*)d_in[4];
    const float* wv = (const float*)d_in[5];
    const float* bv = (const float*)d_in[6];
    const float* wo = (const float*)d_in[7];
    const float* bo = (const float*)d_in[8];

    float* out  = (float*)d_out;
    float* attn = out + (size_t)MTOT * DM;   // tuple order: (out, attn)

    static cudaStream_t s1 = nullptr;
    static cudaEvent_t ev_fork = nullptr, ev_join = nullptr;
    static bool init_done = false;
    if (!init_done) {
        cudaFuncSetAttribute(qkv_mma_kernel,     cudaFuncAttributeMaxDynamicSharedMemorySize, GQ_SMEM);
        cudaFuncSetAttribute(outproj_mma_kernel, cudaFuncAttributeMaxDynamicSharedMemorySize, GQ_SMEM);
        cudaFuncSetAttribute(fattn_a_kernel,     cudaFuncAttributeMaxDynamicSharedMemorySize, FA_SMEM);
        cudaFuncSetAttribute(fattn_b_kernel,     cudaFuncAttributeMaxDynamicSharedMemorySize, FB_SMEM);
        cudaStreamCreateWithFlags(&s1, cudaStreamNonBlocking);
        cudaEventCreateWithFlags(&ev_fork, cudaEventDisableTiming);
        cudaEventCreateWithFlags(&ev_join, cudaEventDisableTiming);
        init_done = true;
    }

    {
        __half *xh, *wqh, *wkh, *wvh, *woh;
        cudaGetSymbolAddress((void**)&xh,  g_xh);
        cudaGetSymbolAddress((void**)&wqh, g_wq);
        cudaGetSymbolAddress((void**)&wkh, g_wk);
        cudaGetSymbolAddress((void**)&wvh, g_wv);
        cudaGetSymbolAddress((void**)&woh, g_wo);

        int n4x = MTOT*DM/4, n4w = DM*DM/4;
        tohalf_kernel<<<(n4x+255)/256, 256>>>((const float4*)x, (uint2*)xh, n4x);
        dim3 gw((n4w+255)/256, 4);
        tohalf4_kernel<<<gw, 256>>>((const float4*)wq, (const float4*)wk,
                                    (const float4*)wv, (const float4*)wo,
                                    (uint2*)wqh, (uint2*)wkh, (uint2*)wvh, (uint2*)woh, n4w);
    }

    dim3 g1(8, 32, 3);
    qkv_mma_kernel<<<g1, 256, GQ_SMEM>>>(bq, bk, bv);

    dim3 g2(16, 32);
    fattn_a_kernel<<<g2, 256, FA_SMEM>>>();

    // fork: outproj (needs g_ohf) runs on s1, concurrent with fattn_b (default)
    cudaEventRecord(ev_fork, 0);
    cudaStreamWaitEvent(s1, ev_fork, 0);

    dim3 g3(8, 32);
    outproj_mma_kernel<<<g3, 256, GQ_SMEM, s1>>>(bo, out);
    cudaEventRecord(ev_join, s1);

    fattn_b_kernel<<<g2, 256, FB_SMEM>>>(attn);

    // join
    cudaStreamWaitEvent(0, ev_join, 0);
}

// round 9
// speedup vs baseline: 1.1395x; 1.1395x over previous
#include <cuda_runtime.h>
#include <cuda_bf16.h>
#include <cuda_fp16.h>
#include <math.h>
#include <stdint.h>

#define BD   2
#define SEQ  2048
#define DM   1024
#define NH   16
#define DH   64
#define MTOT (BD*SEQ)    // 4096
#define BHT  (BD*NH)     // 32

// Q pre-scale: 0.125 * log2(e) so scores arrive in log2 units
#define QSCALE 0.18033688011112042f
#define ONESH2 0x3C003C00u

// ---------------------------------------------------------------------------
// scratch (__device__ globals; allocation-free rule)
// ---------------------------------------------------------------------------
__device__ __half g_q  [BHT*SEQ*DH];     // RoPE'd Q (pre-scaled), fp16 [bh][s][d]
__device__ __half g_k  [BHT*SEQ*DH];     // RoPE'd K
__device__ __half g_v  [BHT*SEQ*DH];     // V
__device__ __half g_xh [MTOT*DM];        // x in fp16
__device__ __half g_wq [DM*DM], g_wk[DM*DM], g_wv[DM*DM], g_wo[DM*DM];
__device__ __half g_ohf[MTOT*DM];        // head outputs [token][dmodel] fp16

// ---------------------------------------------------------------------------
// helpers
// ---------------------------------------------------------------------------
__device__ __forceinline__ uint32_t smem_u32(const void* p) {
    uint32_t a;
    asm("{ .reg .u64 t; cvta.to.shared.u64 t, %1; cvt.u32.u64 %0, t; }" : "=r"(a) : "l"(p));
    return a;
}
__device__ __forceinline__ void ldsm4(uint32_t r[4], uint32_t addr) {
    asm volatile("ldmatrix.sync.aligned.m8n8.x4.shared.b16 {%0,%1,%2,%3}, [%4];"
        : "=r"(r[0]), "=r"(r[1]), "=r"(r[2]), "=r"(r[3]) : "r"(addr));
}
__device__ __forceinline__ void ldsm4t(uint32_t r[4], uint32_t addr) {
    asm volatile("ldmatrix.sync.aligned.m8n8.x4.trans.shared.b16 {%0,%1,%2,%3}, [%4];"
        : "=r"(r[0]), "=r"(r[1]), "=r"(r[2]), "=r"(r[3]) : "r"(addr));
}
__device__ __forceinline__ void mmah(float* c, const uint32_t* a, uint32_t b0, uint32_t b1) {
    asm volatile("mma.sync.aligned.m16n8k16.row.col.f32.f16.f16.f32 "
        "{%0,%1,%2,%3}, {%4,%5,%6,%7}, {%8,%9}, {%0,%1,%2,%3};"
        : "+f"(c[0]), "+f"(c[1]), "+f"(c[2]), "+f"(c[3])
        : "r"(a[0]), "r"(a[1]), "r"(a[2]), "r"(a[3]), "r"(b0), "r"(b1));
}
__device__ __forceinline__ void cp16(uint32_t dst, const void* src) {
    asm volatile("cp.async.cg.shared.global [%0], [%1], 16;" :: "r"(dst), "l"(src));
}
#define CP_COMMIT() asm volatile("cp.async.commit_group;" ::: "memory")
#define CP_WAIT0()  asm volatile("cp.async.wait_group 0;" ::: "memory")
#define SW(o) ((o) ^ (((o) >> 3) & 0x70))

__device__ __forceinline__ uint32_t h2pack(float a, float b) {
    __half2 h = __floats2half2_rn(a, b);
    return *(uint32_t*)&h;
}
__device__ __forceinline__ uint32_t cvt_f16x2(float hi, float lo) {
    uint32_t d; asm("cvt.rn.f16x2.f32 %0, %1, %2;" : "=r"(d) : "f"(hi), "f"(lo)); return d;
}
__device__ __forceinline__ uint32_t ex2_f16x2(uint32_t a) {
    uint32_t d; asm("ex2.approx.f16x2 %0, %1;" : "=r"(d) : "r"(a)); return d;
}
__device__ __forceinline__ float ex2f(float a) {
    float d; asm("ex2.approx.f32 %0, %1;" : "=f"(d) : "f"(a)); return d;
}

// ---------------------------------------------------------------------------
// prep: fp32 -> fp16
// ---------------------------------------------------------------------------
__global__ __launch_bounds__(256) void tohalf_kernel(
    const float4* __restrict__ src, uint2* __restrict__ dst, int n4)
{
    int i = blockIdx.x * 256 + threadIdx.x;
    if (i >= n4) return;
    float4 v = src[i];
    uint2 o;
    o.x = h2pack(v.x, v.y);
    o.y = h2pack(v.z, v.w);
    dst[i] = o;
}

__global__ __launch_bounds__(256) void tohalf4_kernel(
    const float4* __restrict__ s0, const float4* __restrict__ s1,
    const float4* __restrict__ s2, const float4* __restrict__ s3,
    uint2* __restrict__ d0, uint2* __restrict__ d1,
    uint2* __restrict__ d2, uint2* __restrict__ d3, int n4)
{
    int y = blockIdx.y;
    const float4* s = (y==0) ? s0 : (y==1) ? s1 : (y==2) ? s2 : s3;
    uint2* d       = (y==0) ? d0 : (y==1) ? d1 : (y==2) ? d2 : d3;
    int i = blockIdx.x * 256 + threadIdx.x;
    if (i >= n4) return;
    float4 v = s[i];
    uint2 o;
    o.x = h2pack(v.x, v.y);
    o.y = h2pack(v.z, v.w);
    d[i] = o;
}

// ---------------------------------------------------------------------------
// GEMM core (fp16 HMMA, cp.async 2-stage): C(128x128) = A(128xK) @ B(KxN)
// ---------------------------------------------------------------------------
#define GQ_STG  32768
#define GQ_FREQ 65536
#define GQ_SMEM (GQ_FREQ + 128)

__device__ __forceinline__ void gemm_prefetch(
    uint32_t sb, int buf, int tid, int m0, int n0, int k0,
    const __half* A, int lda, const __half* B, int ldb)
{
    const uint32_t ab = sb + buf*GQ_STG;
    const uint32_t bb = ab + 16384;
    #pragma unroll
    for (int i = 0; i < 4; i++) {
        int c = tid + i*256;
        int row = c >> 3, part = c & 7;
        cp16(ab + SW((uint32_t)(row*128 + part*16)), A + (size_t)(m0+row)*lda + k0 + part*8);
    }
    #pragma unroll
    for (int i = 0; i < 4; i++) {
        int c = tid + i*256;
        int krow = c >> 4, chunk = c & 15;
        int half_ = chunk >> 3, nl = (chunk & 7) * 8;
        cp16(bb + (uint32_t)(half_*8192) + SW((uint32_t)(krow*128 + nl*2)),
             B + (size_t)(k0+krow)*ldb + n0 + chunk*8);
    }
}

__device__ __forceinline__ void gemm_tile_mma_h(
    uint32_t base, int lane, int wy, int wx, float acc[4][4][4])
{
    const uint32_t ba = base, bbb = base + 16384;
    const int g = lane >> 3;
    const int arow = wy*64 + (lane & 7) + ((lane >> 3) & 1) * 8;
    #pragma unroll
    for (int ks = 0; ks < 4; ks++) {
        uint32_t a[4][4];
        const uint32_t abase = (uint32_t)(arow*128 + ks*32 + (lane & 16));
        #pragma unroll
        for (int mt = 0; mt < 4; mt++)
            ldsm4(a[mt], ba + SW(abase + mt*16*128));
        #pragma unroll
        for (int np = 0; np < 2; np++) {
            const int krow = ks*16 + (g & 1)*8 + (lane & 7);
            const int nlg = wx*32 + np*16 + (g >> 1)*8;
            const uint32_t boff = (uint32_t)((nlg >> 6)*8192) + SW((uint32_t)(krow*128 + (nlg & 63)*2));
            uint32_t b[4];
            ldsm4t(b, bbb + boff);
            #pragma unroll
            for (int mt = 0; mt < 4; mt++) {
                mmah(acc[mt][np*2+0], a[mt], b[0], b[1]);
                mmah(acc[mt][np*2+1], a[mt], b[2], b[3]);
            }
        }
    }
}

// ---------------------------------------------------------------------------
// QKV projection; epilogue: +bias, RoPE (q,k), Q pre-scaled, store fp16
// ---------------------------------------------------------------------------
__global__ __launch_bounds__(256) void qkv_mma_kernel(
    const float* __restrict__ bq, const float* __restrict__ bk, const float* __restrict__ bv)
{
    extern __shared__ __align__(1024) char smem[];
    const uint32_t sb = smem_u32(smem);
    const int tid = threadIdx.x, wid = tid >> 5, lane = tid & 31;
    const int wy = wid >> 2, wx = wid & 3;
    const int n0 = blockIdx.x * 128;
    const int m0 = blockIdx.y * 128;
    const int z = blockIdx.z;

    const __half* B    = (z==0) ? g_wq : (z==1) ? g_wk : g_wv;
    const float* bias  = (z==0) ? bq   : (z==1) ? bk   : bv;

    float* s_freq = (float*)(smem + GQ_FREQ);
    if (tid < 32)
        s_freq[tid] = (float)(1.0 / pow(10000.0, (double)(2*tid) / 64.0));

    float acc[4][4][4];
    #pragma unroll
    for (int a = 0; a < 4; a++)
        #pragma unroll
        for (int b = 0; b < 4; b++)
            #pragma unroll
            for (int c = 0; c < 4; c++) acc[a][b][c] = 0.f;

    gemm_prefetch(sb, 0, tid, m0, n0, 0, g_xh, DM, B, DM);
    CP_COMMIT();
    for (int kt = 0; kt < 16; kt++) {
        CP_WAIT0();
        __syncthreads();
        if (kt < 15) {
            gemm_prefetch(sb, (kt+1) & 1, tid, m0, n0, (kt+1)*64, g_xh, DM, B, DM);
            CP_COMMIT();
        }
        gemm_tile_mma_h(sb + (kt & 1)*GQ_STG, lane, wy, wx, acc);
    }

    __half* dst = (z==0) ? g_q : (z==1) ? g_k : g_v;
    const int gr = lane >> 2, qc = (lane & 3) * 2;
    #pragma unroll
    for (int mt = 0; mt < 4; mt++) {
        #pragma unroll
        for (int h = 0; h < 2; h++) {
            int r = m0 + wy*64 + mt*16 + h*8 + gr;
            int bb = r >> 11;
            int s  = r & 2047;
            #pragma unroll
            for (int nt = 0; nt < 4; nt++) {
                int c = n0 + wx*32 + nt*8 + qc;   // even col
                float v0 = acc[mt][nt][h*2+0] + bias[c];
                float v1 = acc[mt][nt][h*2+1] + bias[c+1];
                float ox = v0, oy = v1;
                if (z < 2) {
                    float fr = s_freq[(c & 63) >> 1];
                    float sn, cs;
                    sincosf((float)s * fr, &sn, &cs);
                    ox = v0*cs - v1*sn;
                    oy = v0*sn + v1*cs;
                    if (z == 0) { ox *= QSCALE; oy *= QSCALE; }
                }
                int bh = bb*NH + (c >> 6);
                size_t idx = ((size_t)bh*SEQ + s)*DH + (c & 63);
                *(uint32_t*)(dst + idx) = h2pack(ox, oy);
            }
        }
    }
}

// ---------------------------------------------------------------------------
// Fused attention, TWO-PASS, retiled: 128-thread CTA, 4 warps x 32 m-rows.
// Per 64-key chunk, keys processed in two 32-key halves (bounds S regs).
// Pass A: S=QK^T, P=ex2.f16x2(S), rowsum via ones-MMA, PV accumulate.
// Pass B: recompute S, write ex2f(S)*inv normalized attn once (streaming).
// ---------------------------------------------------------------------------
#define FA_SQ   0
#define FA_K0   16384
#define FA_K1   24576
#define FA_V0   32768
#define FA_V1   40960
#define FA_SMEM 49152

__device__ __forceinline__ void fa_prefetch_kv(uint32_t sb, int buf, int bh, int k0, int tid)
{
    const __half* kp = g_k + ((size_t)bh*SEQ + k0)*DH;
    const __half* vp = g_v + ((size_t)bh*SEQ + k0)*DH;
    const uint32_t kb = sb + (buf ? FA_K1 : FA_K0);
    const uint32_t vb = sb + (buf ? FA_V1 : FA_V0);
    #pragma unroll
    for (int i = 0; i < 4; i++) {
        int c = tid + i*128;
        int row = c >> 3, part = c & 7;
        uint32_t off = SW((uint32_t)(row*128 + part*16));
        cp16(kb + off, kp + (size_t)row*DH + part*8);
        cp16(vb + off, vp + (size_t)row*DH + part*8);
    }
}

__device__ __forceinline__ void fa_prefetch_k(uint32_t sb, int buf, int bh, int k0, int tid)
{
    const __half* kp = g_k + ((size_t)bh*SEQ + k0)*DH;
    const uint32_t kb = sb + (buf ? FA_K1 : FA_K0);
    #pragma unroll
    for (int i = 0; i < 4; i++) {
        int c = tid + i*128;
        int row = c >> 3, part = c & 7;
        cp16(kb + SW((uint32_t)(row*128 + part*16)), kp + (size_t)row*DH + part*8);
    }
}

__global__ __launch_bounds__(128) void fattn_kernel(float* __restrict__ attn)
{
    extern __shared__ __align__(1024) char smem[];
    const uint32_t sb = smem_u32(smem);
    const int tid = threadIdx.x, wid = tid >> 5, lane = tid & 31;
    const int m0 = blockIdx.x * 128;
    const int bh = blockIdx.y;
    const int g = lane >> 3, gr = lane >> 2, qc = (lane & 3) * 2;

    // load Q tile (128 x 64 fp16, swizzled); 128 threads x 8 iters
    {
        const uint4* qsrc = (const uint4*)(g_q + ((size_t)bh*SEQ + m0)*DH);
        #pragma unroll
        for (int i = 0; i < 8; i++) {
            int c = tid + i*128;
            int row = c >> 3, part = c & 7;
            *(uint4*)(smem + FA_SQ + SW((uint32_t)(row*128 + part*16))) = qsrc[row*8 + part];
        }
    }
    fa_prefetch_kv(sb, 0, bh, 0, tid);
    CP_COMMIT();
    __syncthreads();

    // per-warp persistent Q fragments: 2 m-tiles (32 rows) x 64 k
    uint32_t qf[2][4][4];
    #pragma unroll
    for (int mt = 0; mt < 2; mt++) {
        const int arow = wid*32 + mt*16 + (lane & 7) + ((lane >> 3) & 1)*8;
        #pragma unroll
        for (int ks = 0; ks < 4; ks++)
            ldsm4(qf[mt][ks], sb + FA_SQ + SW((uint32_t)(arow*128 + ks*32 + (lane & 16))));
    }

    float o[2][8][4];
    #pragma unroll
    for (int mt = 0; mt < 2; mt++)
        #pragma unroll
        for (int t = 0; t < 8; t++)
            #pragma unroll
            for (int j = 0; j < 4; j++) o[mt][t][j] = 0.f;
    float ors[2][4] = {{0.f,0.f,0.f,0.f},{0.f,0.f,0.f,0.f}};

    // ------------------- PASS A: rowsum + PV (no gmem writes) ---------------
    for (int kt = 0; kt < 32; kt++) {
        CP_WAIT0();
        __syncthreads();
        if (kt < 31) { fa_prefetch_kv(sb, (kt+1) & 1, bh, (kt+1)*64, tid); CP_COMMIT(); }

        const uint32_t kb = sb + ((kt & 1) ? FA_K1 : FA_K0);
        const uint32_t vb = sb + ((kt & 1) ? FA_V1 : FA_V0);

        #pragma unroll
        for (int nh = 0; nh < 2; nh++) {       // 32-key halves
            float S[2][4][4];
            #pragma unroll
            for (int mt = 0; mt < 2; mt++)
                #pragma unroll
                for (int t = 0; t < 4; t++)
                    #pragma unroll
                    for (int j = 0; j < 4; j++) S[mt][t][j] = 0.f;

            #pragma unroll
            for (int np = 0; np < 2; np++) {
                const int nrow = nh*32 + np*16 + (g >> 1)*8 + (lane & 7);
                #pragma unroll
                for (int ks = 0; ks < 4; ks++) {
                    uint32_t bK[4];
                    ldsm4(bK, kb + SW((uint32_t)(nrow*128 + ks*32 + (g & 1)*16)));
                    #pragma unroll
                    for (int mt = 0; mt < 2; mt++) {
                        mmah(S[mt][np*2+0], qf[mt][ks], bK[0], bK[1]);
                        mmah(S[mt][np*2+1], qf[mt][ks], bK[2], bK[3]);
                    }
                }
            }

            uint32_t P01[2][4], P23[2][4];
            #pragma unroll
            for (int mt = 0; mt < 2; mt++)
                #pragma unroll
                for (int t = 0; t < 4; t++) {
                    P01[mt][t] = ex2_f16x2(cvt_f16x2(S[mt][t][1], S[mt][t][0]));
                    P23[mt][t] = ex2_f16x2(cvt_f16x2(S[mt][t][3], S[mt][t][2]));
                }

            #pragma unroll
            for (int kk = 0; kk < 2; kk++) {   // 16-key slices within half
                uint32_t aP[2][4];
                #pragma unroll
                for (int mt = 0; mt < 2; mt++) {
                    aP[mt][0] = P01[mt][2*kk];   aP[mt][1] = P23[mt][2*kk];
                    aP[mt][2] = P01[mt][2*kk+1]; aP[mt][3] = P23[mt][2*kk+1];
                    mmah(ors[mt], aP[mt], ONESH2, ONESH2);
                }
                const int krow = nh*32 + kk*16 + (g & 1)*8 + (lane & 7);
                #pragma unroll
                for (int np = 0; np < 4; np++) {
                    const int ncol = np*16 + (g >> 1)*8;
                    uint32_t bV[4];
                    ldsm4t(bV, vb + SW((uint32_t)(krow*128 + ncol*2)));
                    #pragma unroll
                    for (int mt = 0; mt < 2; mt++) {
                        mmah(o[mt][np*2+0], aP[mt], bV[0], bV[1]);
                        mmah(o[mt][np*2+1], aP[mt], bV[2], bV[3]);
                    }
                }
            }
        }
    }

    float inv[2][2];
    #pragma unroll
    for (int mt = 0; mt < 2; mt++) {
        inv[mt][0] = 1.f / ors[mt][0];
        inv[mt][1] = 1.f / ors[mt][2];
    }

    // all warps done reading pass-A buffers before pass B overwrites K0
    __syncthreads();
    fa_prefetch_k(sb, 0, bh, 0, tid);
    CP_COMMIT();

    // overlap: write normalized head outputs (fp16) while cp.async flies
    const int bb = bh >> 4, hh = bh & 15;
    #pragma unroll
    for (int mt = 0; mt < 2; mt++) {
        const int row0 = m0 + wid*32 + mt*16 + gr;
        __half* o0 = g_ohf + ((size_t)bb*SEQ + row0)*DM + hh*64;
        __half* o1 = o0 + 8*DM;
        #pragma unroll
        for (int t = 0; t < 8; t++) {
            *(uint32_t*)(o0 + t*8 + qc) = h2pack(o[mt][t][0]*inv[mt][0], o[mt][t][1]*inv[mt][0]);
            *(uint32_t*)(o1 + t*8 + qc) = h2pack(o[mt][t][2]*inv[mt][1], o[mt][t][3]*inv[mt][1]);
        }
    }

    // ------------------- PASS B: recompute S, write normalized attn ---------
    float* arow[2][2];
    #pragma unroll
    for (int mt = 0; mt < 2; mt++) {
        const int row0 = m0 + wid*32 + mt*16 + gr;
        arow[mt][0] = attn + ((size_t)bh*SEQ + row0)*SEQ;
        arow[mt][1] = arow[mt][0] + 8*SEQ;
    }

    for (int kt = 0; kt < 32; kt++) {
        CP_WAIT0();
        __syncthreads();
        if (kt < 31) { fa_prefetch_k(sb, (kt+1) & 1, bh, (kt+1)*64, tid); CP_COMMIT(); }

        const uint32_t kb = sb + ((kt & 1) ? FA_K1 : FA_K0);

        #pragma unroll
        for (int nh = 0; nh < 2; nh++) {
            float S[2][4][4];
            #pragma unroll
            for (int mt = 0; mt < 2; mt++)
                #pragma unroll
                for (int t = 0; t < 4; t++)
                    #pragma unroll
                    for (int j = 0; j < 4; j++) S[mt][t][j] = 0.f;

            #pragma unroll
            for (int np = 0; np < 2; np++) {
                const int nrow = nh*32 + np*16 + (g >> 1)*8 + (lane & 7);
                #pragma unroll
                for (int ks = 0; ks < 4; ks++) {
                    uint32_t bK[4];
                    ldsm4(bK, kb + SW((uint32_t)(nrow*128 + ks*32 + (g & 1)*16)));
                    #pragma unroll
                    for (int mt = 0; mt < 2; mt++) {
                        mmah(S[mt][np*2+0], qf[mt][ks], bK[0], bK[1]);
                        mmah(S[mt][np*2+1], qf[mt][ks], bK[2], bK[3]);
                    }
                }
            }

            #pragma unroll
            for (int mt = 0; mt < 2; mt++)
                #pragma unroll
                for (int t = 0; t < 4; t++) {
                    float e0 = ex2f(S[mt][t][0]) * inv[mt][0];
                    float e1 = ex2f(S[mt][t][1]) * inv[mt][0];
                    float e2 = ex2f(S[mt][t][2]) * inv[mt][1];
                    float e3 = ex2f(S[mt][t][3]) * inv[mt][1];
                    int col = kt*64 + nh*32 + t*8 + qc;
                    __stcs((float2*)(arow[mt][0] + col), make_float2(e0, e1));
                    __stcs((float2*)(arow[mt][1] + col), make_float2(e2, e3));
                }
        }
    }
}

// ---------------------------------------------------------------------------
// Output projection: out = oh @ Wo + bo
// ---------------------------------------------------------------------------
__global__ __launch_bounds__(256) void outproj_mma_kernel(
    const float* __restrict__ bo, float* __restrict__ out)
{
    extern __shared__ __align__(1024) char smem[];
    const uint32_t sb = smem_u32(smem);
    const int tid = threadIdx.x, wid = tid >> 5, lane = tid & 31;
    const int wy = wid >> 2, wx = wid & 3;
    const int n0 = blockIdx.x * 128;
    const int m0 = blockIdx.y * 128;

    float acc[4][4][4];
    #pragma unroll
    for (int a = 0; a < 4; a++)
        #pragma unroll
        for (int b = 0; b < 4; b++)
            #pragma unroll
            for (int c = 0; c < 4; c++) acc[a][b][c] = 0.f;

    gemm_prefetch(sb, 0, tid, m0, n0, 0, g_ohf, DM, g_wo, DM);
    CP_COMMIT();
    for (int kt = 0; kt < 16; kt++) {
        CP_WAIT0();
        __syncthreads();
        if (kt < 15) {
            gemm_prefetch(sb, (kt+1) & 1, tid, m0, n0, (kt+1)*64, g_ohf, DM, g_wo, DM);
            CP_COMMIT();
        }
        gemm_tile_mma_h(sb + (kt & 1)*GQ_STG, lane, wy, wx, acc);
    }

    const int gr = lane >> 2, qc = (lane & 3) * 2;
    #pragma unroll
    for (int mt = 0; mt < 4; mt++) {
        #pragma unroll
        for (int h = 0; h < 2; h++) {
            int r = m0 + wy*64 + mt*16 + h*8 + gr;
            #pragma unroll
            for (int nt = 0; nt < 4; nt++) {
                int c = n0 + wx*32 + nt*8 + qc;
                float2 oo;
                oo.x = acc[mt][nt][h*2+0] + bo[c];
                oo.y = acc[mt][nt][h*2+1] + bo[c+1];
                *(float2*)(out + (size_t)r*DM + c) = oo;
            }
        }
    }
}

// ---------------------------------------------------------------------------
extern "C" void kernel_launch(void* const* d_in, const int* in_sizes, int n_in,
                              void* d_out, int out_size)
{
    const float* x  = (const float*)d_in[0];
    const float* wq = (const float*)d_in[1];
    const float* bq = (const float*)d_in[2];
    const float* wk = (const float*)d_in[3];
    const float* bk = (const float*)d_in[4];
    const float* wv = (const float*)d_in[5];
    const float* bv = (const float*)d_in[6];
    const float* wo = (const float*)d_in[7];
    const float* bo = (const float*)d_in[8];

    float* out  = (float*)d_out;
    float* attn = out + (size_t)MTOT * DM;   // tuple order: (out, attn)

    static bool init_done = false;
    if (!init_done) {
        cudaFuncSetAttribute(qkv_mma_kernel,     cudaFuncAttributeMaxDynamicSharedMemorySize, GQ_SMEM);
        cudaFuncSetAttribute(outproj_mma_kernel, cudaFuncAttributeMaxDynamicSharedMemorySize, GQ_SMEM);
        cudaFuncSetAttribute(fattn_kernel,       cudaFuncAttributeMaxDynamicSharedMemorySize, FA_SMEM);
        init_done = true;
    }

    {
        __half *xh, *wqh, *wkh, *wvh, *woh;
        cudaGetSymbolAddress((void**)&xh,  g_xh);
        cudaGetSymbolAddress((void**)&wqh, g_wq);
        cudaGetSymbolAddress((void**)&wkh, g_wk);
        cudaGetSymbolAddress((void**)&wvh, g_wv);
        cudaGetSymbolAddress((void**)&woh, g_wo);

        int n4x = MTOT*DM/4, n4w = DM*DM/4;
        tohalf_kernel<<<(n4x+255)/256, 256>>>((const float4*)x, (uint2*)xh, n4x);
        dim3 gw((n4w+255)/256, 4);
        tohalf4_kernel<<<gw, 256>>>((const float4*)wq, (const float4*)wk,
                                    (const float4*)wv, (const float4*)wo,
                                    (uint2*)wqh, (uint2*)wkh, (uint2*)wvh, (uint2*)woh, n4w);
    }

    dim3 g1(8, 32, 3);
    qkv_mma_kernel<<<g1, 256, GQ_SMEM>>>(bq, bk, bv);

    dim3 g2(16, 32);
    fattn_kernel<<<g2, 128, FA_SMEM>>>(attn);

    dim3 g3(8, 32);
    outproj_mma_kernel<<<g3, 256, GQ_SMEM>>>(bo, out);
}

// round 10
// speedup vs baseline: 1.1535x; 1.0123x over previous
#include <cuda_runtime.h>
#include <cuda_bf16.h>
#include <cuda_fp16.h>
#include <math.h>
#include <stdint.h>

#define BD   2
#define SEQ  2048
#define DM   1024
#define NH   16
#define DH   64
#define MTOT (BD*SEQ)    // 4096
#define BHT  (BD*NH)     // 32

// Q pre-scale: 0.125 * log2(e) so scores arrive in log2 units
#define QSCALE 0.18033688011112042f
#define ONESH2 0x3C003C00u

// ---------------------------------------------------------------------------
// scratch (__device__ globals; allocation-free rule)
// ---------------------------------------------------------------------------
__device__ __half g_q  [BHT*SEQ*DH];     // RoPE'd Q (pre-scaled), fp16 [bh][s][d]
__device__ __half g_k  [BHT*SEQ*DH];     // RoPE'd K
__device__ __half g_v  [BHT*SEQ*DH];     // V
__device__ __half g_xh [MTOT*DM];        // x in fp16
__device__ __half g_wq [DM*DM], g_wk[DM*DM], g_wv[DM*DM], g_wo[DM*DM];
__device__ __half g_ohf[MTOT*DM];        // head outputs [token][dmodel] fp16
__device__ float2 g_rope[SEQ*32];        // (cos, sin) per (s, freq-pair)

// ---------------------------------------------------------------------------
// helpers
// ---------------------------------------------------------------------------
__device__ __forceinline__ uint32_t smem_u32(const void* p) {
    uint32_t a;
    asm("{ .reg .u64 t; cvta.to.shared.u64 t, %1; cvt.u32.u64 %0, t; }" : "=r"(a) : "l"(p));
    return a;
}
__device__ __forceinline__ void ldsm4(uint32_t r[4], uint32_t addr) {
    asm volatile("ldmatrix.sync.aligned.m8n8.x4.shared.b16 {%0,%1,%2,%3}, [%4];"
        : "=r"(r[0]), "=r"(r[1]), "=r"(r[2]), "=r"(r[3]) : "r"(addr));
}
__device__ __forceinline__ void ldsm4t(uint32_t r[4], uint32_t addr) {
    asm volatile("ldmatrix.sync.aligned.m8n8.x4.trans.shared.b16 {%0,%1,%2,%3}, [%4];"
        : "=r"(r[0]), "=r"(r[1]), "=r"(r[2]), "=r"(r[3]) : "r"(addr));
}
__device__ __forceinline__ void mmah(float* c, const uint32_t* a, uint32_t b0, uint32_t b1) {
    asm volatile("mma.sync.aligned.m16n8k16.row.col.f32.f16.f16.f32 "
        "{%0,%1,%2,%3}, {%4,%5,%6,%7}, {%8,%9}, {%0,%1,%2,%3};"
        : "+f"(c[0]), "+f"(c[1]), "+f"(c[2]), "+f"(c[3])
        : "r"(a[0]), "r"(a[1]), "r"(a[2]), "r"(a[3]), "r"(b0), "r"(b1));
}
__device__ __forceinline__ void cp16(uint32_t dst, const void* src) {
    asm volatile("cp.async.cg.shared.global [%0], [%1], 16;" :: "r"(dst), "l"(src));
}
#define CP_COMMIT() asm volatile("cp.async.commit_group;" ::: "memory")
#define CP_WAIT0()  asm volatile("cp.async.wait_group 0;" ::: "memory")
#define SW(o) ((o) ^ (((o) >> 3) & 0x70))

__device__ __forceinline__ uint32_t h2pack(float a, float b) {
    __half2 h = __floats2half2_rn(a, b);
    return *(uint32_t*)&h;
}
__device__ __forceinline__ uint32_t cvt_f16x2(float hi, float lo) {
    uint32_t d; asm("cvt.rn.f16x2.f32 %0, %1, %2;" : "=r"(d) : "f"(hi), "f"(lo)); return d;
}
__device__ __forceinline__ uint32_t ex2_f16x2(uint32_t a) {
    uint32_t d; asm("ex2.approx.f16x2 %0, %1;" : "=r"(d) : "r"(a)); return d;
}
__device__ __forceinline__ float ex2f(float a) {
    float d; asm("ex2.approx.f32 %0, %1;" : "=f"(d) : "f"(a)); return d;
}

// ---------------------------------------------------------------------------
// prep: fp32 -> fp16  +  RoPE table
// ---------------------------------------------------------------------------
__global__ __launch_bounds__(256) void tohalf_kernel(
    const float4* __restrict__ src, uint2* __restrict__ dst, int n4)
{
    int i = blockIdx.x * 256 + threadIdx.x;
    if (i >= n4) return;
    float4 v = src[i];
    uint2 o;
    o.x = h2pack(v.x, v.y);
    o.y = h2pack(v.z, v.w);
    dst[i] = o;
}

__global__ __launch_bounds__(256) void tohalf4_kernel(
    const float4* __restrict__ s0, const float4* __restrict__ s1,
    const float4* __restrict__ s2, const float4* __restrict__ s3,
    uint2* __restrict__ d0, uint2* __restrict__ d1,
    uint2* __restrict__ d2, uint2* __restrict__ d3, int n4)
{
    int y = blockIdx.y;
    const float4* s = (y==0) ? s0 : (y==1) ? s1 : (y==2) ? s2 : s3;
    uint2* d       = (y==0) ? d0 : (y==1) ? d1 : (y==2) ? d2 : d3;
    int i = blockIdx.x * 256 + threadIdx.x;
    if (i >= n4) return;
    float4 v = s[i];
    uint2 o;
    o.x = h2pack(v.x, v.y);
    o.y = h2pack(v.z, v.w);
    d[i] = o;
}

__global__ __launch_bounds__(256) void rope_table_kernel()
{
    int i = blockIdx.x * 256 + threadIdx.x;   // i < SEQ*32
    int s = i >> 5, j = i & 31;
    float fr = (float)(1.0 / pow(10000.0, (double)(2*j) / 64.0));
    float sn, cs;
    sincosf((float)s * fr, &sn, &cs);
    g_rope[i] = make_float2(cs, sn);
}

// ---------------------------------------------------------------------------
// GEMM core (fp16 HMMA, cp.async 2-stage): C(128x128) = A(128xK) @ B(KxN)
// ---------------------------------------------------------------------------
#define GQ_STG  32768
#define GQ_SMEM (2*GQ_STG)

__device__ __forceinline__ void gemm_prefetch(
    uint32_t sb, int buf, int tid, int m0, int n0, int k0,
    const __half* A, int lda, const __half* B, int ldb)
{
    const uint32_t ab = sb + buf*GQ_STG;
    const uint32_t bb = ab + 16384;
    #pragma unroll
    for (int i = 0; i < 4; i++) {
        int c = tid + i*256;
        int row = c >> 3, part = c & 7;
        cp16(ab + SW((uint32_t)(row*128 + part*16)), A + (size_t)(m0+row)*lda + k0 + part*8);
    }
    #pragma unroll
    for (int i = 0; i < 4; i++) {
        int c = tid + i*256;
        int krow = c >> 4, chunk = c & 15;
        int half_ = chunk >> 3, nl = (chunk & 7) * 8;
        cp16(bb + (uint32_t)(half_*8192) + SW((uint32_t)(krow*128 + nl*2)),
             B + (size_t)(k0+krow)*ldb + n0 + chunk*8);
    }
}

__device__ __forceinline__ void gemm_tile_mma_h(
    uint32_t base, int lane, int wy, int wx, float acc[4][4][4])
{
    const uint32_t ba = base, bbb = base + 16384;
    const int g = lane >> 3;
    const int arow = wy*64 + (lane & 7) + ((lane >> 3) & 1) * 8;
    #pragma unroll
    for (int ks = 0; ks < 4; ks++) {
        uint32_t a[4][4];
        const uint32_t abase = (uint32_t)(arow*128 + ks*32 + (lane & 16));
        #pragma unroll
        for (int mt = 0; mt < 4; mt++)
            ldsm4(a[mt], ba + SW(abase + mt*16*128));
        #pragma unroll
        for (int np = 0; np < 2; np++) {
            const int krow = ks*16 + (g & 1)*8 + (lane & 7);
            const int nlg = wx*32 + np*16 + (g >> 1)*8;
            const uint32_t boff = (uint32_t)((nlg >> 6)*8192) + SW((uint32_t)(krow*128 + (nlg & 63)*2));
            uint32_t b[4];
            ldsm4t(b, bbb + boff);
            #pragma unroll
            for (int mt = 0; mt < 4; mt++) {
                mmah(acc[mt][np*2+0], a[mt], b[0], b[1]);
                mmah(acc[mt][np*2+1], a[mt], b[2], b[3]);
            }
        }
    }
}

// ---------------------------------------------------------------------------
// QKV projection; epilogue: +bias, RoPE via table (q,k), Q pre-scaled
// ---------------------------------------------------------------------------
__global__ __launch_bounds__(256) void qkv_mma_kernel(
    const float* __restrict__ bq, const float* __restrict__ bk, const float* __restrict__ bv)
{
    extern __shared__ __align__(1024) char smem[];
    const uint32_t sb = smem_u32(smem);
    const int tid = threadIdx.x, wid = tid >> 5, lane = tid & 31;
    const int wy = wid >> 2, wx = wid & 3;
    const int n0 = blockIdx.x * 128;
    const int m0 = blockIdx.y * 128;
    const int z = blockIdx.z;

    const __half* B    = (z==0) ? g_wq : (z==1) ? g_wk : g_wv;
    const float* bias  = (z==0) ? bq   : (z==1) ? bk   : bv;

    float acc[4][4][4];
    #pragma unroll
    for (int a = 0; a < 4; a++)
        #pragma unroll
        for (int b = 0; b < 4; b++)
            #pragma unroll
            for (int c = 0; c < 4; c++) acc[a][b][c] = 0.f;

    gemm_prefetch(sb, 0, tid, m0, n0, 0, g_xh, DM, B, DM);
    CP_COMMIT();
    for (int kt = 0; kt < 16; kt++) {
        CP_WAIT0();
        __syncthreads();
        if (kt < 15) {
            gemm_prefetch(sb, (kt+1) & 1, tid, m0, n0, (kt+1)*64, g_xh, DM, B, DM);
            CP_COMMIT();
        }
        gemm_tile_mma_h(sb + (kt & 1)*GQ_STG, lane, wy, wx, acc);
    }

    __half* dst = (z==0) ? g_q : (z==1) ? g_k : g_v;
    const int gr = lane >> 2, qc = (lane & 3) * 2;
    #pragma unroll
    for (int mt = 0; mt < 4; mt++) {
        #pragma unroll
        for (int h = 0; h < 2; h++) {
            int r = m0 + wy*64 + mt*16 + h*8 + gr;
            int bb = r >> 11;
            int s  = r & 2047;
            #pragma unroll
            for (int nt = 0; nt < 4; nt++) {
                int c = n0 + wx*32 + nt*8 + qc;   // even col
                float v0 = acc[mt][nt][h*2+0] + bias[c];
                float v1 = acc[mt][nt][h*2+1] + bias[c+1];
                float ox = v0, oy = v1;
                if (z < 2) {
                    float2 cssn = g_rope[s*32 + ((c & 63) >> 1)];
                    ox = v0*cssn.x - v1*cssn.y;
                    oy = v0*cssn.y + v1*cssn.x;
                    if (z == 0) { ox *= QSCALE; oy *= QSCALE; }
                }
                int bh = bb*NH + (c >> 6);
                size_t idx = ((size_t)bh*SEQ + s)*DH + (c & 63);
                *(uint32_t*)(dst + idx) = h2pack(ox, oy);
            }
        }
    }
}

// ---------------------------------------------------------------------------
// Fused attention, TWO-PASS, 128-thread CTA, 4 warps x 32 m-rows.
// Pass A: S=QK^T, P=ex2.f16x2(S), rowsum via ones-MMA, PV accumulate.
// Pass B: recompute S, write ex2f(S)*inv normalized attn once (streaming).
// ---------------------------------------------------------------------------
#define FA_SQ   0
#define FA_K0   16384
#define FA_K1   24576
#define FA_V0   32768
#define FA_V1   40960
#define FA_SMEM 49152

__device__ __forceinline__ void fa_prefetch_kv(uint32_t sb, int buf, int bh, int k0, int tid)
{
    const __half* kp = g_k + ((size_t)bh*SEQ + k0)*DH;
    const __half* vp = g_v + ((size_t)bh*SEQ + k0)*DH;
    const uint32_t kb = sb + (buf ? FA_K1 : FA_K0);
    const uint32_t vb = sb + (buf ? FA_V1 : FA_V0);
    #pragma unroll
    for (int i = 0; i < 4; i++) {
        int c = tid + i*128;
        int row = c >> 3, part = c & 7;
        uint32_t off = SW((uint32_t)(row*128 + part*16));
        cp16(kb + off, kp + (size_t)row*DH + part*8);
        cp16(vb + off, vp + (size_t)row*DH + part*8);
    }
}

__device__ __forceinline__ void fa_prefetch_k(uint32_t sb, int buf, int bh, int k0, int tid)
{
    const __half* kp = g_k + ((size_t)bh*SEQ + k0)*DH;
    const uint32_t kb = sb + (buf ? FA_K1 : FA_K0);
    #pragma unroll
    for (int i = 0; i < 4; i++) {
        int c = tid + i*128;
        int row = c >> 3, part = c & 7;
        cp16(kb + SW((uint32_t)(row*128 + part*16)), kp + (size_t)row*DH + part*8);
    }
}

__global__ __launch_bounds__(128) void fattn_kernel(float* __restrict__ attn)
{
    extern __shared__ __align__(1024) char smem[];
    const uint32_t sb = smem_u32(smem);
    const int tid = threadIdx.x, wid = tid >> 5, lane = tid & 31;
    const int m0 = blockIdx.x * 128;
    const int bh = blockIdx.y;
    const int g = lane >> 3, gr = lane >> 2, qc = (lane & 3) * 2;

    // load Q tile (128 x 64 fp16, swizzled); 128 threads x 8 iters
    {
        const uint4* qsrc = (const uint4*)(g_q + ((size_t)bh*SEQ + m0)*DH);
        #pragma unroll
        for (int i = 0; i < 8; i++) {
            int c = tid + i*128;
            int row = c >> 3, part = c & 7;
            *(uint4*)(smem + FA_SQ + SW((uint32_t)(row*128 + part*16))) = qsrc[row*8 + part];
        }
    }
    fa_prefetch_kv(sb, 0, bh, 0, tid);
    CP_COMMIT();
    __syncthreads();

    // per-warp persistent Q fragments: 2 m-tiles (32 rows) x 64 k
    uint32_t qf[2][4][4];
    #pragma unroll
    for (int mt = 0; mt < 2; mt++) {
        const int arow = wid*32 + mt*16 + (lane & 7) + ((lane >> 3) & 1)*8;
        #pragma unroll
        for (int ks = 0; ks < 4; ks++)
            ldsm4(qf[mt][ks], sb + FA_SQ + SW((uint32_t)(arow*128 + ks*32 + (lane & 16))));
    }

    float o[2][8][4];
    #pragma unroll
    for (int mt = 0; mt < 2; mt++)
        #pragma unroll
        for (int t = 0; t < 8; t++)
            #pragma unroll
            for (int j = 0; j < 4; j++) o[mt][t][j] = 0.f;
    float ors[2][4] = {{0.f,0.f,0.f,0.f},{0.f,0.f,0.f,0.f}};

    // ------------------- PASS A: rowsum + PV (no gmem writes) ---------------
    for (int kt = 0; kt < 32; kt++) {
        CP_WAIT0();
        __syncthreads();
        if (kt < 31) { fa_prefetch_kv(sb, (kt+1) & 1, bh, (kt+1)*64, tid); CP_COMMIT(); }

        const uint32_t kb = sb + ((kt & 1) ? FA_K1 : FA_K0);
        const uint32_t vb = sb + ((kt & 1) ? FA_V1 : FA_V0);

        #pragma unroll
        for (int nh = 0; nh < 2; nh++) {       // 32-key halves
            float S[2][4][4];
            #pragma unroll
            for (int mt = 0; mt < 2; mt++)
                #pragma unroll
                for (int t = 0; t < 4; t++)
                    #pragma unroll
                    for (int j = 0; j < 4; j++) S[mt][t][j] = 0.f;

            #pragma unroll
            for (int np = 0; np < 2; np++) {
                const int nrow = nh*32 + np*16 + (g >> 1)*8 + (lane & 7);
                #pragma unroll
                for (int ks = 0; ks < 4; ks++) {
                    uint32_t bK[4];
                    ldsm4(bK, kb + SW((uint32_t)(nrow*128 + ks*32 + (g & 1)*16)));
                    #pragma unroll
                    for (int mt = 0; mt < 2; mt++) {
                        mmah(S[mt][np*2+0], qf[mt][ks], bK[0], bK[1]);
                        mmah(S[mt][np*2+1], qf[mt][ks], bK[2], bK[3]);
                    }
                }
            }

            uint32_t P01[2][4], P23[2][4];
            #pragma unroll
            for (int mt = 0; mt < 2; mt++)
                #pragma unroll
                for (int t = 0; t < 4; t++) {
                    P01[mt][t] = ex2_f16x2(cvt_f16x2(S[mt][t][1], S[mt][t][0]));
                    P23[mt][t] = ex2_f16x2(cvt_f16x2(S[mt][t][3], S[mt][t][2]));
                }

            #pragma unroll
            for (int kk = 0; kk < 2; kk++) {   // 16-key slices within half
                uint32_t aP[2][4];
                #pragma unroll
                for (int mt = 0; mt < 2; mt++) {
                    aP[mt][0] = P01[mt][2*kk];   aP[mt][1] = P23[mt][2*kk];
                    aP[mt][2] = P01[mt][2*kk+1]; aP[mt][3] = P23[mt][2*kk+1];
                    mmah(ors[mt], aP[mt], ONESH2, ONESH2);
                }
                const int krow = nh*32 + kk*16 + (g & 1)*8 + (lane & 7);
                #pragma unroll
                for (int np = 0; np < 4; np++) {
                    const int ncol = np*16 + (g >> 1)*8;
                    uint32_t bV[4];
                    ldsm4t(bV, vb + SW((uint32_t)(krow*128 + ncol*2)));
                    #pragma unroll
                    for (int mt = 0; mt < 2; mt++) {
                        mmah(o[mt][np*2+0], aP[mt], bV[0], bV[1]);
                        mmah(o[mt][np*2+1], aP[mt], bV[2], bV[3]);
                    }
                }
            }
        }
    }

    float inv[2][2];
    #pragma unroll
    for (int mt = 0; mt < 2; mt++) {
        inv[mt][0] = 1.f / ors[mt][0];
        inv[mt][1] = 1.f / ors[mt][2];
    }

    // all warps done reading pass-A buffers before pass B overwrites K0
    __syncthreads();
    fa_prefetch_k(sb, 0, bh, 0, tid);
    CP_COMMIT();

    // overlap: write normalized head outputs (fp16) while cp.async flies
    const int bb = bh >> 4, hh = bh & 15;
    #pragma unroll
    for (int mt = 0; mt < 2; mt++) {
        const int row0 = m0 + wid*32 + mt*16 + gr;
        __half* o0 = g_ohf + ((size_t)bb*SEQ + row0)*DM + hh*64;
        __half* o1 = o0 + 8*DM;
        #pragma unroll
        for (int t = 0; t < 8; t++) {
            *(uint32_t*)(o0 + t*8 + qc) = h2pack(o[mt][t][0]*inv[mt][0], o[mt][t][1]*inv[mt][0]);
            *(uint32_t*)(o1 + t*8 + qc) = h2pack(o[mt][t][2]*inv[mt][1], o[mt][t][3]*inv[mt][1]);
        }
    }

    // ------------------- PASS B: recompute S, write normalized attn ---------
    float* arow[2][2];
    #pragma unroll
    for (int mt = 0; mt < 2; mt++) {
        const int row0 = m0 + wid*32 + mt*16 + gr;
        arow[mt][0] = attn + ((size_t)bh*SEQ + row0)*SEQ;
        arow[mt][1] = arow[mt][0] + 8*SEQ;
    }

    for (int kt = 0; kt < 32; kt++) {
        CP_WAIT0();
        __syncthreads();
        if (kt < 31) { fa_prefetch_k(sb, (kt+1) & 1, bh, (kt+1)*64, tid); CP_COMMIT(); }

        const uint32_t kb = sb + ((kt & 1) ? FA_K1 : FA_K0);

        #pragma unroll
        for (int nh = 0; nh < 2; nh++) {
            float S[2][4][4];
            #pragma unroll
            for (int mt = 0; mt < 2; mt++)
                #pragma unroll
                for (int t = 0; t < 4; t++)
                    #pragma unroll
                    for (int j = 0; j < 4; j++) S[mt][t][j] = 0.f;

            #pragma unroll
            for (int np = 0; np < 2; np++) {
                const int nrow = nh*32 + np*16 + (g >> 1)*8 + (lane & 7);
                #pragma unroll
                for (int ks = 0; ks < 4; ks++) {
                    uint32_t bK[4];
                    ldsm4(bK, kb + SW((uint32_t)(nrow*128 + ks*32 + (g & 1)*16)));
                    #pragma unroll
                    for (int mt = 0; mt < 2; mt++) {
                        mmah(S[mt][np*2+0], qf[mt][ks], bK[0], bK[1]);
                        mmah(S[mt][np*2+1], qf[mt][ks], bK[2], bK[3]);
                    }
                }
            }

            #pragma unroll
            for (int mt = 0; mt < 2; mt++)
                #pragma unroll
                for (int t = 0; t < 4; t++) {
                    float e0 = ex2f(S[mt][t][0]) * inv[mt][0];
                    float e1 = ex2f(S[mt][t][1]) * inv[mt][0];
                    float e2 = ex2f(S[mt][t][2]) * inv[mt][1];
                    float e3 = ex2f(S[mt][t][3]) * inv[mt][1];
                    int col = kt*64 + nh*32 + t*8 + qc;
                    __stcs((float2*)(arow[mt][0] + col), make_float2(e0, e1));
                    __stcs((float2*)(arow[mt][1] + col), make_float2(e2, e3));
                }
        }
    }
}

// ---------------------------------------------------------------------------
// Output projection: out = oh @ Wo + bo
// ---------------------------------------------------------------------------
__global__ __launch_bounds__(256) void outproj_mma_kernel(
    const float* __restrict__ bo, float* __restrict__ out)
{
    extern __shared__ __align__(1024) char smem[];
    const uint32_t sb = smem_u32(smem);
    const int tid = threadIdx.x, wid = tid >> 5, lane = tid & 31;
    const int wy = wid >> 2, wx = wid & 3;
    const int n0 = blockIdx.x * 128;
    const int m0 = blockIdx.y * 128;

    float acc[4][4][4];
    #pragma unroll
    for (int a = 0; a < 4; a++)
        #pragma unroll
        for (int b = 0; b < 4; b++)
            #pragma unroll
            for (int c = 0; c < 4; c++) acc[a][b][c] = 0.f;

    gemm_prefetch(sb, 0, tid, m0, n0, 0, g_ohf, DM, g_wo, DM);
    CP_COMMIT();
    for (int kt = 0; kt < 16; kt++) {
        CP_WAIT0();
        __syncthreads();
        if (kt < 15) {
            gemm_prefetch(sb, (kt+1) & 1, tid, m0, n0, (kt+1)*64, g_ohf, DM, g_wo, DM);
            CP_COMMIT();
        }
        gemm_tile_mma_h(sb + (kt & 1)*GQ_STG, lane, wy, wx, acc);
    }

    const int gr = lane >> 2, qc = (lane & 3) * 2;
    #pragma unroll
    for (int mt = 0; mt < 4; mt++) {
        #pragma unroll
        for (int h = 0; h < 2; h++) {
            int r = m0 + wy*64 + mt*16 + h*8 + gr;
            #pragma unroll
            for (int nt = 0; nt < 4; nt++) {
                int c = n0 + wx*32 + nt*8 + qc;
                float2 oo;
                oo.x = acc[mt][nt][h*2+0] + bo[c];
                oo.y = acc[mt][nt][h*2+1] + bo[c+1];
                *(float2*)(out + (size_t)r*DM + c) = oo;
            }
        }
    }
}

// ---------------------------------------------------------------------------
extern "C" void kernel_launch(void* const* d_in, const int* in_sizes, int n_in,
                              void* d_out, int out_size)
{
    const float* x  = (const float*)d_in[0];
    const float* wq = (const float*)d_in[1];
    const float* bq = (const float*)d_in[2];
    const float* wk = (const float*)d_in[3];
    const float* bk = (const float*)d_in[4];
    const float* wv = (const float*)d_in[5];
    const float* bv = (const float*)d_in[6];
    const float* wo = (const float*)d_in[7];
    const float* bo = (const float*)d_in[8];

    float* out  = (float*)d_out;
    float* attn = out + (size_t)MTOT * DM;   // tuple order: (out, attn)

    static bool init_done = false;
    if (!init_done) {
        cudaFuncSetAttribute(qkv_mma_kernel,     cudaFuncAttributeMaxDynamicSharedMemorySize, GQ_SMEM);
        cudaFuncSetAttribute(outproj_mma_kernel, cudaFuncAttributeMaxDynamicSharedMemorySize, GQ_SMEM);
        cudaFuncSetAttribute(fattn_kernel,       cudaFuncAttributeMaxDynamicSharedMemorySize, FA_SMEM);
        init_done = true;
    }

    {
        __half *xh, *wqh, *wkh, *wvh, *woh;
        cudaGetSymbolAddress((void**)&xh,  g_xh);
        cudaGetSymbolAddress((void**)&wqh, g_wq);
        cudaGetSymbolAddress((void**)&wkh, g_wk);
        cudaGetSymbolAddress((void**)&wvh, g_wv);
        cudaGetSymbolAddress((void**)&woh, g_wo);

        int n4x = MTOT*DM/4, n4w = DM*DM/4;
        rope_table_kernel<<<SEQ*32/256, 256>>>();
        tohalf_kernel<<<(n4x+255)/256, 256>>>((const float4*)x, (uint2*)xh, n4x);
        dim3 gw((n4w+255)/256, 4);
        tohalf4_kernel<<<gw, 256>>>((const float4*)wq, (const float4*)wk,
                                    (const float4*)wv, (const float4*)wo,
                                    (uint2*)wqh, (uint2*)wkh, (uint2*)wvh, (uint2*)woh, n4w);
    }

    dim3 g1(8, 32, 3);
    qkv_mma_kernel<<<g1, 256, GQ_SMEM>>>(bq, bk, bv);

    dim3 g2(16, 32);
    fattn_kernel<<<g2, 128, FA_SMEM>>>(attn);

    dim3 g3(8, 32);
    outproj_mma_kernel<<<g3, 256, GQ_SMEM>>>(bo, out);
}

// round 11
// speedup vs baseline: 1.2407x; 1.0756x over previous
#include <cuda_runtime.h>
#include <cuda_bf16.h>
#include <cuda_fp16.h>
#include <math.h>
#include <stdint.h>

#define BD   2
#define SEQ  2048
#define DM   1024
#define NH   16
#define DH   64
#define MTOT (BD*SEQ)    // 4096
#define BHT  (BD*NH)     // 32

// Q pre-scale: 0.125 * log2(e) so scores arrive in log2 units
#define QSCALE 0.18033688011112042f
#define ONESH2 0x3C003C00u

// ---------------------------------------------------------------------------
// scratch (__device__ globals; allocation-free rule)
// ---------------------------------------------------------------------------
__device__ __half g_q  [BHT*SEQ*DH];     // RoPE'd Q (pre-scaled), fp16 [bh][s][d]
__device__ __half g_k  [BHT*SEQ*DH];     // RoPE'd K
__device__ __half g_v  [BHT*SEQ*DH];     // V
__device__ __half g_xh [MTOT*DM];        // x in fp16
__device__ __half g_wq [DM*DM], g_wk[DM*DM], g_wv[DM*DM], g_wo[DM*DM];
__device__ __half g_ohf[MTOT*DM];        // head outputs [token][dmodel] fp16
__device__ float2 g_rope[SEQ*32];        // (cos, sin) per (s, freq-pair)

// ---------------------------------------------------------------------------
// helpers
// ---------------------------------------------------------------------------
__device__ __forceinline__ uint32_t smem_u32(const void* p) {
    uint32_t a;
    asm("{ .reg .u64 t; cvta.to.shared.u64 t, %1; cvt.u32.u64 %0, t; }" : "=r"(a) : "l"(p));
    return a;
}
__device__ __forceinline__ void ldsm4(uint32_t r[4], uint32_t addr) {
    asm volatile("ldmatrix.sync.aligned.m8n8.x4.shared.b16 {%0,%1,%2,%3}, [%4];"
        : "=r"(r[0]), "=r"(r[1]), "=r"(r[2]), "=r"(r[3]) : "r"(addr));
}
__device__ __forceinline__ void ldsm4t(uint32_t r[4], uint32_t addr) {
    asm volatile("ldmatrix.sync.aligned.m8n8.x4.trans.shared.b16 {%0,%1,%2,%3}, [%4];"
        : "=r"(r[0]), "=r"(r[1]), "=r"(r[2]), "=r"(r[3]) : "r"(addr));
}
__device__ __forceinline__ void mmah(float* c, const uint32_t* a, uint32_t b0, uint32_t b1) {
    asm volatile("mma.sync.aligned.m16n8k16.row.col.f32.f16.f16.f32 "
        "{%0,%1,%2,%3}, {%4,%5,%6,%7}, {%8,%9}, {%0,%1,%2,%3};"
        : "+f"(c[0]), "+f"(c[1]), "+f"(c[2]), "+f"(c[3])
        : "r"(a[0]), "r"(a[1]), "r"(a[2]), "r"(a[3]), "r"(b0), "r"(b1));
}
__device__ __forceinline__ void cp16(uint32_t dst, const void* src) {
    asm volatile("cp.async.cg.shared.global [%0], [%1], 16;" :: "r"(dst), "l"(src));
}
#define CP_COMMIT() asm volatile("cp.async.commit_group;" ::: "memory")
#define CP_WAIT0()  asm volatile("cp.async.wait_group 0;" ::: "memory")
#define SW(o) ((o) ^ (((o) >> 3) & 0x70))

__device__ __forceinline__ uint32_t h2pack(float a, float b) {
    __half2 h = __floats2half2_rn(a, b);
    return *(uint32_t*)&h;
}
__device__ __forceinline__ uint32_t cvt_f16x2(float hi, float lo) {
    uint32_t d; asm("cvt.rn.f16x2.f32 %0, %1, %2;" : "=r"(d) : "f"(hi), "f"(lo)); return d;
}
__device__ __forceinline__ uint32_t ex2_f16x2(uint32_t a) {
    uint32_t d; asm("ex2.approx.f16x2 %0, %1;" : "=r"(d) : "r"(a)); return d;
}
__device__ __forceinline__ float ex2f(float a) {
    float d; asm("ex2.approx.f32 %0, %1;" : "=f"(d) : "f"(a)); return d;
}

// ---------------------------------------------------------------------------
// prep: fp32 -> fp16  +  RoPE table
// ---------------------------------------------------------------------------
__global__ __launch_bounds__(256) void tohalf_kernel(
    const float4* __restrict__ src, uint2* __restrict__ dst, int n4)
{
    int i = blockIdx.x * 256 + threadIdx.x;
    if (i >= n4) return;
    float4 v = src[i];
    uint2 o;
    o.x = h2pack(v.x, v.y);
    o.y = h2pack(v.z, v.w);
    dst[i] = o;
}

__global__ __launch_bounds__(256) void tohalf4_kernel(
    const float4* __restrict__ s0, const float4* __restrict__ s1,
    const float4* __restrict__ s2, const float4* __restrict__ s3,
    uint2* __restrict__ d0, uint2* __restrict__ d1,
    uint2* __restrict__ d2, uint2* __restrict__ d3, int n4)
{
    int y = blockIdx.y;
    const float4* s = (y==0) ? s0 : (y==1) ? s1 : (y==2) ? s2 : s3;
    uint2* d       = (y==0) ? d0 : (y==1) ? d1 : (y==2) ? d2 : d3;
    int i = blockIdx.x * 256 + threadIdx.x;
    if (i >= n4) return;
    float4 v = s[i];
    uint2 o;
    o.x = h2pack(v.x, v.y);
    o.y = h2pack(v.z, v.w);
    d[i] = o;
}

__global__ __launch_bounds__(256) void rope_table_kernel()
{
    int i = blockIdx.x * 256 + threadIdx.x;   // i < SEQ*32
    int s = i >> 5, j = i & 31;
    float fr = (float)(1.0 / pow(10000.0, (double)(2*j) / 64.0));
    float sn, cs;
    sincosf((float)s * fr, &sn, &cs);
    g_rope[i] = make_float2(cs, sn);
}

// ---------------------------------------------------------------------------
// GEMM core (fp16 HMMA, cp.async 2-stage): C(128x128) = A(128xK) @ B(KxN)
// ---------------------------------------------------------------------------
#define GQ_STG  32768
#define GQ_SMEM (2*GQ_STG)

__device__ __forceinline__ void gemm_prefetch(
    uint32_t sb, int buf, int tid, int m0, int n0, int k0,
    const __half* A, int lda, const __half* B, int ldb)
{
    const uint32_t ab = sb + buf*GQ_STG;
    const uint32_t bb = ab + 16384;
    #pragma unroll
    for (int i = 0; i < 4; i++) {
        int c = tid + i*256;
        int row = c >> 3, part = c & 7;
        cp16(ab + SW((uint32_t)(row*128 + part*16)), A + (size_t)(m0+row)*lda + k0 + part*8);
    }
    #pragma unroll
    for (int i = 0; i < 4; i++) {
        int c = tid + i*256;
        int krow = c >> 4, chunk = c & 15;
        int half_ = chunk >> 3, nl = (chunk & 7) * 8;
        cp16(bb + (uint32_t)(half_*8192) + SW((uint32_t)(krow*128 + nl*2)),
             B + (size_t)(k0+krow)*ldb + n0 + chunk*8);
    }
}

__device__ __forceinline__ void gemm_tile_mma_h(
    uint32_t base, int lane, int wy, int wx, float acc[4][4][4])
{
    const uint32_t ba = base, bbb = base + 16384;
    const int g = lane >> 3;
    const int arow = wy*64 + (lane & 7) + ((lane >> 3) & 1) * 8;
    #pragma unroll
    for (int ks = 0; ks < 4; ks++) {
        uint32_t a[4][4];
        const uint32_t abase = (uint32_t)(arow*128 + ks*32 + (lane & 16));
        #pragma unroll
        for (int mt = 0; mt < 4; mt++)
            ldsm4(a[mt], ba + SW(abase + mt*16*128));
        #pragma unroll
        for (int np = 0; np < 2; np++) {
            const int krow = ks*16 + (g & 1)*8 + (lane & 7);
            const int nlg = wx*32 + np*16 + (g >> 1)*8;
            const uint32_t boff = (uint32_t)((nlg >> 6)*8192) + SW((uint32_t)(krow*128 + (nlg & 63)*2));
            uint32_t b[4];
            ldsm4t(b, bbb + boff);
            #pragma unroll
            for (int mt = 0; mt < 4; mt++) {
                mmah(acc[mt][np*2+0], a[mt], b[0], b[1]);
                mmah(acc[mt][np*2+1], a[mt], b[2], b[3]);
            }
        }
    }
}

// ---------------------------------------------------------------------------
// QKV projection; epilogue: +bias, RoPE via table (q,k), Q pre-scaled
// __launch_bounds__(256,2): cap regs at 128 -> 2 CTAs/SM for latency hiding
// ---------------------------------------------------------------------------
__global__ __launch_bounds__(256, 2) void qkv_mma_kernel(
    const float* __restrict__ bq, const float* __restrict__ bk, const float* __restrict__ bv)
{
    extern __shared__ __align__(1024) char smem[];
    const uint32_t sb = smem_u32(smem);
    const int tid = threadIdx.x, wid = tid >> 5, lane = tid & 31;
    const int wy = wid >> 2, wx = wid & 3;
    const int n0 = blockIdx.x * 128;
    const int m0 = blockIdx.y * 128;
    const int z = blockIdx.z;

    const __half* B    = (z==0) ? g_wq : (z==1) ? g_wk : g_wv;
    const float* bias  = (z==0) ? bq   : (z==1) ? bk   : bv;

    float acc[4][4][4];
    #pragma unroll
    for (int a = 0; a < 4; a++)
        #pragma unroll
        for (int b = 0; b < 4; b++)
            #pragma unroll
            for (int c = 0; c < 4; c++) acc[a][b][c] = 0.f;

    gemm_prefetch(sb, 0, tid, m0, n0, 0, g_xh, DM, B, DM);
    CP_COMMIT();
    for (int kt = 0; kt < 16; kt++) {
        CP_WAIT0();
        __syncthreads();
        if (kt < 15) {
            gemm_prefetch(sb, (kt+1) & 1, tid, m0, n0, (kt+1)*64, g_xh, DM, B, DM);
            CP_COMMIT();
        }
        gemm_tile_mma_h(sb + (kt & 1)*GQ_STG, lane, wy, wx, acc);
    }

    __half* dst = (z==0) ? g_q : (z==1) ? g_k : g_v;
    const int gr = lane >> 2, qc = (lane & 3) * 2;
    #pragma unroll
    for (int mt = 0; mt < 4; mt++) {
        #pragma unroll
        for (int h = 0; h < 2; h++) {
            int r = m0 + wy*64 + mt*16 + h*8 + gr;
            int bb = r >> 11;
            int s  = r & 2047;
            #pragma unroll
            for (int nt = 0; nt < 4; nt++) {
                int c = n0 + wx*32 + nt*8 + qc;   // even col
                float v0 = acc[mt][nt][h*2+0] + bias[c];
                float v1 = acc[mt][nt][h*2+1] + bias[c+1];
                float ox = v0, oy = v1;
                if (z < 2) {
                    float2 cssn = g_rope[s*32 + ((c & 63) >> 1)];
                    ox = v0*cssn.x - v1*cssn.y;
                    oy = v0*cssn.y + v1*cssn.x;
                    if (z == 0) { ox *= QSCALE; oy *= QSCALE; }
                }
                int bh = bb*NH + (c >> 6);
                size_t idx = ((size_t)bh*SEQ + s)*DH + (c & 63);
                *(uint32_t*)(dst + idx) = h2pack(ox, oy);
            }
        }
    }
}

// ---------------------------------------------------------------------------
// Fused attention, TWO-PASS, 128-thread CTA, 4 warps x 32 m-rows.
// ---------------------------------------------------------------------------
#define FA_SQ   0
#define FA_K0   16384
#define FA_K1   24576
#define FA_V0   32768
#define FA_V1   40960
#define FA_SMEM 49152

__device__ __forceinline__ void fa_prefetch_kv(uint32_t sb, int buf, int bh, int k0, int tid)
{
    const __half* kp = g_k + ((size_t)bh*SEQ + k0)*DH;
    const __half* vp = g_v + ((size_t)bh*SEQ + k0)*DH;
    const uint32_t kb = sb + (buf ? FA_K1 : FA_K0);
    const uint32_t vb = sb + (buf ? FA_V1 : FA_V0);
    #pragma unroll
    for (int i = 0; i < 4; i++) {
        int c = tid + i*128;
        int row = c >> 3, part = c & 7;
        uint32_t off = SW((uint32_t)(row*128 + part*16));
        cp16(kb + off, kp + (size_t)row*DH + part*8);
        cp16(vb + off, vp + (size_t)row*DH + part*8);
    }
}

__device__ __forceinline__ void fa_prefetch_k(uint32_t sb, int buf, int bh, int k0, int tid)
{
    const __half* kp = g_k + ((size_t)bh*SEQ + k0)*DH;
    const uint32_t kb = sb + (buf ? FA_K1 : FA_K0);
    #pragma unroll
    for (int i = 0; i < 4; i++) {
        int c = tid + i*128;
        int row = c >> 3, part = c & 7;
        cp16(kb + SW((uint32_t)(row*128 + part*16)), kp + (size_t)row*DH + part*8);
    }
}

__global__ __launch_bounds__(128) void fattn_kernel(float* __restrict__ attn)
{
    extern __shared__ __align__(1024) char smem[];
    const uint32_t sb = smem_u32(smem);
    const int tid = threadIdx.x, wid = tid >> 5, lane = tid & 31;
    const int m0 = blockIdx.x * 128;
    const int bh = blockIdx.y;
    const int g = lane >> 3, gr = lane >> 2, qc = (lane & 3) * 2;

    // load Q tile (128 x 64 fp16, swizzled); 128 threads x 8 iters
    {
        const uint4* qsrc = (const uint4*)(g_q + ((size_t)bh*SEQ + m0)*DH);
        #pragma unroll
        for (int i = 0; i < 8; i++) {
            int c = tid + i*128;
            int row = c >> 3, part = c & 7;
            *(uint4*)(smem + FA_SQ + SW((uint32_t)(row*128 + part*16))) = qsrc[row*8 + part];
        }
    }
    fa_prefetch_kv(sb, 0, bh, 0, tid);
    CP_COMMIT();
    __syncthreads();

    // per-warp persistent Q fragments: 2 m-tiles (32 rows) x 64 k
    uint32_t qf[2][4][4];
    #pragma unroll
    for (int mt = 0; mt < 2; mt++) {
        const int arow = wid*32 + mt*16 + (lane & 7) + ((lane >> 3) & 1)*8;
        #pragma unroll
        for (int ks = 0; ks < 4; ks++)
            ldsm4(qf[mt][ks], sb + FA_SQ + SW((uint32_t)(arow*128 + ks*32 + (lane & 16))));
    }

    float o[2][8][4];
    #pragma unroll
    for (int mt = 0; mt < 2; mt++)
        #pragma unroll
        for (int t = 0; t < 8; t++)
            #pragma unroll
            for (int j = 0; j < 4; j++) o[mt][t][j] = 0.f;
    float ors[2][4] = {{0.f,0.f,0.f,0.f},{0.f,0.f,0.f,0.f}};

    // ------------------- PASS A: rowsum + PV (no gmem writes) ---------------
    for (int kt = 0; kt < 32; kt++) {
        CP_WAIT0();
        __syncthreads();
        if (kt < 31) { fa_prefetch_kv(sb, (kt+1) & 1, bh, (kt+1)*64, tid); CP_COMMIT(); }

        const uint32_t kb = sb + ((kt & 1) ? FA_K1 : FA_K0);
        const uint32_t vb = sb + ((kt & 1) ? FA_V1 : FA_V0);

        #pragma unroll
        for (int nh = 0; nh < 2; nh++) {       // 32-key halves
            float S[2][4][4];
            #pragma unroll
            for (int mt = 0; mt < 2; mt++)
                #pragma unroll
                for (int t = 0; t < 4; t++)
                    #pragma unroll
                    for (int j = 0; j < 4; j++) S[mt][t][j] = 0.f;

            #pragma unroll
            for (int np = 0; np < 2; np++) {
                const int nrow = nh*32 + np*16 + (g >> 1)*8 + (lane & 7);
                #pragma unroll
                for (int ks = 0; ks < 4; ks++) {
                    uint32_t bK[4];
                    ldsm4(bK, kb + SW((uint32_t)(nrow*128 + ks*32 + (g & 1)*16)));
                    #pragma unroll
                    for (int mt = 0; mt < 2; mt++) {
                        mmah(S[mt][np*2+0], qf[mt][ks], bK[0], bK[1]);
                        mmah(S[mt][np*2+1], qf[mt][ks], bK[2], bK[3]);
                    }
                }
            }

            uint32_t P01[2][4], P23[2][4];
            #pragma unroll
            for (int mt = 0; mt < 2; mt++)
                #pragma unroll
                for (int t = 0; t < 4; t++) {
                    P01[mt][t] = ex2_f16x2(cvt_f16x2(S[mt][t][1], S[mt][t][0]));
                    P23[mt][t] = ex2_f16x2(cvt_f16x2(S[mt][t][3], S[mt][t][2]));
                }

            #pragma unroll
            for (int kk = 0; kk < 2; kk++) {   // 16-key slices within half
                uint32_t aP[2][4];
                #pragma unroll
                for (int mt = 0; mt < 2; mt++) {
                    aP[mt][0] = P01[mt][2*kk];   aP[mt][1] = P23[mt][2*kk];
                    aP[mt][2] = P01[mt][2*kk+1]; aP[mt][3] = P23[mt][2*kk+1];
                    mmah(ors[mt], aP[mt], ONESH2, ONESH2);
                }
                const int krow = nh*32 + kk*16 + (g & 1)*8 + (lane & 7);
                #pragma unroll
                for (int np = 0; np < 4; np++) {
                    const int ncol = np*16 + (g >> 1)*8;
                    uint32_t bV[4];
                    ldsm4t(bV, vb + SW((uint32_t)(krow*128 + ncol*2)));
                    #pragma unroll
                    for (int mt = 0; mt < 2; mt++) {
                        mmah(o[mt][np*2+0], aP[mt], bV[0], bV[1]);
                        mmah(o[mt][np*2+1], aP[mt], bV[2], bV[3]);
                    }
                }
            }
        }
    }

    float inv[2][2];
    #pragma unroll
    for (int mt = 0; mt < 2; mt++) {
        inv[mt][0] = 1.f / ors[mt][0];
        inv[mt][1] = 1.f / ors[mt][2];
    }

    // all warps done reading pass-A buffers before pass B overwrites K0
    __syncthreads();
    fa_prefetch_k(sb, 0, bh, 0, tid);
    CP_COMMIT();

    // overlap: write normalized head outputs (fp16) while cp.async flies
    const int bb = bh >> 4, hh = bh & 15;
    #pragma unroll
    for (int mt = 0; mt < 2; mt++) {
        const int row0 = m0 + wid*32 + mt*16 + gr;
        __half* o0 = g_ohf + ((size_t)bb*SEQ + row0)*DM + hh*64;
        __half* o1 = o0 + 8*DM;
        #pragma unroll
        for (int t = 0; t < 8; t++) {
            *(uint32_t*)(o0 + t*8 + qc) = h2pack(o[mt][t][0]*inv[mt][0], o[mt][t][1]*inv[mt][0]);
            *(uint32_t*)(o1 + t*8 + qc) = h2pack(o[mt][t][2]*inv[mt][1], o[mt][t][3]*inv[mt][1]);
        }
    }

    // ------------------- PASS B: recompute S, write normalized attn ---------
    float* arow[2][2];
    #pragma unroll
    for (int mt = 0; mt < 2; mt++) {
        const int row0 = m0 + wid*32 + mt*16 + gr;
        arow[mt][0] = attn + ((size_t)bh*SEQ + row0)*SEQ;
        arow[mt][1] = arow[mt][0] + 8*SEQ;
    }

    for (int kt = 0; kt < 32; kt++) {
        CP_WAIT0();
        __syncthreads();
        if (kt < 31) { fa_prefetch_k(sb, (kt+1) & 1, bh, (kt+1)*64, tid); CP_COMMIT(); }

        const uint32_t kb = sb + ((kt & 1) ? FA_K1 : FA_K0);

        #pragma unroll
        for (int nh = 0; nh < 2; nh++) {
            float S[2][4][4];
            #pragma unroll
            for (int mt = 0; mt < 2; mt++)
                #pragma unroll
                for (int t = 0; t < 4; t++)
                    #pragma unroll
                    for (int j = 0; j < 4; j++) S[mt][t][j] = 0.f;

            #pragma unroll
            for (int np = 0; np < 2; np++) {
                const int nrow = nh*32 + np*16 + (g >> 1)*8 + (lane & 7);
                #pragma unroll
                for (int ks = 0; ks < 4; ks++) {
                    uint32_t bK[4];
                    ldsm4(bK, kb + SW((uint32_t)(nrow*128 + ks*32 + (g & 1)*16)));
                    #pragma unroll
                    for (int mt = 0; mt < 2; mt++) {
                        mmah(S[mt][np*2+0], qf[mt][ks], bK[0], bK[1]);
                        mmah(S[mt][np*2+1], qf[mt][ks], bK[2], bK[3]);
                    }
                }
            }

            #pragma unroll
            for (int mt = 0; mt < 2; mt++)
                #pragma unroll
                for (int t = 0; t < 4; t++) {
                    float e0 = ex2f(S[mt][t][0]) * inv[mt][0];
                    float e1 = ex2f(S[mt][t][1]) * inv[mt][0];
                    float e2 = ex2f(S[mt][t][2]) * inv[mt][1];
                    float e3 = ex2f(S[mt][t][3]) * inv[mt][1];
                    int col = kt*64 + nh*32 + t*8 + qc;
                    __stcs((float2*)(arow[mt][0] + col), make_float2(e0, e1));
                    __stcs((float2*)(arow[mt][1] + col), make_float2(e2, e3));
                }
        }
    }
}

// ---------------------------------------------------------------------------
// Output projection: out = oh @ Wo + bo
// ---------------------------------------------------------------------------
__global__ __launch_bounds__(256, 2) void outproj_mma_kernel(
    const float* __restrict__ bo, float* __restrict__ out)
{
    extern __shared__ __align__(1024) char smem[];
    const uint32_t sb = smem_u32(smem);
    const int tid = threadIdx.x, wid = tid >> 5, lane = tid & 31;
    const int wy = wid >> 2, wx = wid & 3;
    const int n0 = blockIdx.x * 128;
    const int m0 = blockIdx.y * 128;

    float acc[4][4][4];
    #pragma unroll
    for (int a = 0; a < 4; a++)
        #pragma unroll
        for (int b = 0; b < 4; b++)
            #pragma unroll
            for (int c = 0; c < 4; c++) acc[a][b][c] = 0.f;

    gemm_prefetch(sb, 0, tid, m0, n0, 0, g_ohf, DM, g_wo, DM);
    CP_COMMIT();
    for (int kt = 0; kt < 16; kt++) {
        CP_WAIT0();
        __syncthreads();
        if (kt < 15) {
            gemm_prefetch(sb, (kt+1) & 1, tid, m0, n0, (kt+1)*64, g_ohf, DM, g_wo, DM);
            CP_COMMIT();
        }
        gemm_tile_mma_h(sb + (kt & 1)*GQ_STG, lane, wy, wx, acc);
    }

    const int gr = lane >> 2, qc = (lane & 3) * 2;
    #pragma unroll
    for (int mt = 0; mt < 4; mt++) {
        #pragma unroll
        for (int h = 0; h < 2; h++) {
            int r = m0 + wy*64 + mt*16 + h*8 + gr;
            #pragma unroll
            for (int nt = 0; nt < 4; nt++) {
                int c = n0 + wx*32 + nt*8 + qc;
                float2 oo;
                oo.x = acc[mt][nt][h*2+0] + bo[c];
                oo.y = acc[mt][nt][h*2+1] + bo[c+1];
                *(float2*)(out + (size_t)r*DM + c) = oo;
            }
        }
    }
}

// ---------------------------------------------------------------------------
extern "C" void kernel_launch(void* const* d_in, const int* in_sizes, int n_in,
                              void* d_out, int out_size)
{
    const float* x  = (const float*)d_in[0];
    const float* wq = (const float*)d_in[1];
    const float* bq = (const float*)d_in[2];
    const float* wk = (const float*)d_in[3];
    const float* bk = (const float*)d_in[4];
    const float* wv = (const float*)d_in[5];
    const float* bv = (const float*)d_in[6];
    const float* wo = (const float*)d_in[7];
    const float* bo = (const float*)d_in[8];

    float* out  = (float*)d_out;
    float* attn = out + (size_t)MTOT * DM;   // tuple order: (out, attn)

    static bool init_done = false;
    if (!init_done) {
        cudaFuncSetAttribute(qkv_mma_kernel,     cudaFuncAttributeMaxDynamicSharedMemorySize, GQ_SMEM);
        cudaFuncSetAttribute(outproj_mma_kernel, cudaFuncAttributeMaxDynamicSharedMemorySize, GQ_SMEM);
        cudaFuncSetAttribute(fattn_kernel,       cudaFuncAttributeMaxDynamicSharedMemorySize, FA_SMEM);
        init_done = true;
    }

    {
        __half *xh, *wqh, *wkh, *wvh, *woh;
        cudaGetSymbolAddress((void**)&xh,  g_xh);
        cudaGetSymbolAddress((void**)&wqh, g_wq);
        cudaGetSymbolAddress((void**)&wkh, g_wk);
        cudaGetSymbolAddress((void**)&wvh, g_wv);
        cudaGetSymbolAddress((void**)&woh, g_wo);

        int n4x = MTOT*DM/4, n4w = DM*DM/4;
        rope_table_kernel<<<SEQ*32/256, 256>>>();
        tohalf_kernel<<<(n4x+255)/256, 256>>>((const float4*)x, (uint2*)xh, n4x);
        dim3 gw((n4w+255)/256, 4);
        tohalf4_kernel<<<gw, 256>>>((const float4*)wq, (const float4*)wk,
                                    (const float4*)wv, (const float4*)wo,
                                    (uint2*)wqh, (uint2*)wkh, (uint2*)wvh, (uint2*)woh, n4w);
    }

    dim3 g1(8, 32, 3);
    qkv_mma_kernel<<<g1, 256, GQ_SMEM>>>(bq, bk, bv);

    dim3 g2(16, 32);
    fattn_kernel<<<g2, 128, FA_SMEM>>>(attn);

    dim3 g3(8, 32);
    outproj_mma_kernel<<<g3, 256, GQ_SMEM>>>(bo, out);
}

// round 12
// speedup vs baseline: 1.2420x; 1.0011x over previous
#include <cuda_runtime.h>
#include <cuda_bf16.h>
#include <cuda_fp16.h>
#include <math.h>
#include <stdint.h>

#define BD   2
#define SEQ  2048
#define DM   1024
#define NH   16
#define DH   64
#define MTOT (BD*SEQ)    // 4096
#define BHT  (BD*NH)     // 32

// Q pre-scale: 0.125 * log2(e) so scores arrive in log2 units
#define QSCALE 0.18033688011112042f
#define ONESH2 0x3C003C00u

// ---------------------------------------------------------------------------
// scratch (__device__ globals; allocation-free rule)
// ---------------------------------------------------------------------------
__device__ __half g_q  [BHT*SEQ*DH];     // RoPE'd Q (pre-scaled), fp16 [bh][s][d]
__device__ __half g_k  [BHT*SEQ*DH];     // RoPE'd K
__device__ __half g_v  [BHT*SEQ*DH];     // V
__device__ __half g_xh [MTOT*DM];        // x in fp16
__device__ __half g_wq [DM*DM], g_wk[DM*DM], g_wv[DM*DM], g_wo[DM*DM];
__device__ __half g_ohf[MTOT*DM];        // head outputs [token][dmodel] fp16
__device__ float2 g_rope[SEQ*32];        // (cos, sin) per (s, freq-pair)

// ---------------------------------------------------------------------------
// helpers
// ---------------------------------------------------------------------------
__device__ __forceinline__ uint32_t smem_u32(const void* p) {
    uint32_t a;
    asm("{ .reg .u64 t; cvta.to.shared.u64 t, %1; cvt.u32.u64 %0, t; }" : "=r"(a) : "l"(p));
    return a;
}
__device__ __forceinline__ void ldsm4(uint32_t r[4], uint32_t addr) {
    asm volatile("ldmatrix.sync.aligned.m8n8.x4.shared.b16 {%0,%1,%2,%3}, [%4];"
        : "=r"(r[0]), "=r"(r[1]), "=r"(r[2]), "=r"(r[3]) : "r"(addr));
}
__device__ __forceinline__ void ldsm4t(uint32_t r[4], uint32_t addr) {
    asm volatile("ldmatrix.sync.aligned.m8n8.x4.trans.shared.b16 {%0,%1,%2,%3}, [%4];"
        : "=r"(r[0]), "=r"(r[1]), "=r"(r[2]), "=r"(r[3]) : "r"(addr));
}
__device__ __forceinline__ void mmah(float* c, const uint32_t* a, uint32_t b0, uint32_t b1) {
    asm volatile("mma.sync.aligned.m16n8k16.row.col.f32.f16.f16.f32 "
        "{%0,%1,%2,%3}, {%4,%5,%6,%7}, {%8,%9}, {%0,%1,%2,%3};"
        : "+f"(c[0]), "+f"(c[1]), "+f"(c[2]), "+f"(c[3])
        : "r"(a[0]), "r"(a[1]), "r"(a[2]), "r"(a[3]), "r"(b0), "r"(b1));
}
__device__ __forceinline__ void cp16(uint32_t dst, const void* src) {
    asm volatile("cp.async.cg.shared.global [%0], [%1], 16;" :: "r"(dst), "l"(src));
}
#define CP_COMMIT() asm volatile("cp.async.commit_group;" ::: "memory")
#define CP_WAIT0()  asm volatile("cp.async.wait_group 0;" ::: "memory")
#define CP_WAIT1()  asm volatile("cp.async.wait_group 1;" ::: "memory")
#define SW(o) ((o) ^ (((o) >> 3) & 0x70))

__device__ __forceinline__ uint32_t h2pack(float a, float b) {
    __half2 h = __floats2half2_rn(a, b);
    return *(uint32_t*)&h;
}
__device__ __forceinline__ uint32_t cvt_f16x2(float hi, float lo) {
    uint32_t d; asm("cvt.rn.f16x2.f32 %0, %1, %2;" : "=r"(d) : "f"(hi), "f"(lo)); return d;
}
__device__ __forceinline__ uint32_t ex2_f16x2(uint32_t a) {
    uint32_t d; asm("ex2.approx.f16x2 %0, %1;" : "=r"(d) : "r"(a)); return d;
}
__device__ __forceinline__ float ex2f(float a) {
    float d; asm("ex2.approx.f32 %0, %1;" : "=f"(d) : "f"(a)); return d;
}

// ---------------------------------------------------------------------------
// prep: fp32 -> fp16  +  RoPE table
// ---------------------------------------------------------------------------
__global__ __launch_bounds__(256) void tohalf_kernel(
    const float4* __restrict__ src, uint2* __restrict__ dst, int n4)
{
    int i = blockIdx.x * 256 + threadIdx.x;
    if (i >= n4) return;
    float4 v = src[i];
    uint2 o;
    o.x = h2pack(v.x, v.y);
    o.y = h2pack(v.z, v.w);
    dst[i] = o;
}

__global__ __launch_bounds__(256) void tohalf4_kernel(
    const float4* __restrict__ s0, const float4* __restrict__ s1,
    const float4* __restrict__ s2, const float4* __restrict__ s3,
    uint2* __restrict__ d0, uint2* __restrict__ d1,
    uint2* __restrict__ d2, uint2* __restrict__ d3, int n4)
{
    int y = blockIdx.y;
    const float4* s = (y==0) ? s0 : (y==1) ? s1 : (y==2) ? s2 : s3;
    uint2* d       = (y==0) ? d0 : (y==1) ? d1 : (y==2) ? d2 : d3;
    int i = blockIdx.x * 256 + threadIdx.x;
    if (i >= n4) return;
    float4 v = s[i];
    uint2 o;
    o.x = h2pack(v.x, v.y);
    o.y = h2pack(v.z, v.w);
    d[i] = o;
}

__global__ __launch_bounds__(256) void rope_table_kernel()
{
    int i = blockIdx.x * 256 + threadIdx.x;   // i < SEQ*32
    int s = i >> 5, j = i & 31;
    float fr = (float)(1.0 / pow(10000.0, (double)(2*j) / 64.0));
    float sn, cs;
    sincosf((float)s * fr, &sn, &cs);
    g_rope[i] = make_float2(cs, sn);
}

// ---------------------------------------------------------------------------
// GEMM core (fp16 HMMA, cp.async 3-stage): C(128x128) = A(128xK) @ B(KxN)
// ---------------------------------------------------------------------------
#define GQ_STG  32768
#define GQ_SMEM (3*GQ_STG)

__device__ __forceinline__ void gemm_prefetch(
    uint32_t sb, int buf, int tid, int m0, int n0, int k0,
    const __half* A, int lda, const __half* B, int ldb)
{
    const uint32_t ab = sb + buf*GQ_STG;
    const uint32_t bb = ab + 16384;
    #pragma unroll
    for (int i = 0; i < 4; i++) {
        int c = tid + i*256;
        int row = c >> 3, part = c & 7;
        cp16(ab + SW((uint32_t)(row*128 + part*16)), A + (size_t)(m0+row)*lda + k0 + part*8);
    }
    #pragma unroll
    for (int i = 0; i < 4; i++) {
        int c = tid + i*256;
        int krow = c >> 4, chunk = c & 15;
        int half_ = chunk >> 3, nl = (chunk & 7) * 8;
        cp16(bb + (uint32_t)(half_*8192) + SW((uint32_t)(krow*128 + nl*2)),
             B + (size_t)(k0+krow)*ldb + n0 + chunk*8);
    }
}

__device__ __forceinline__ void gemm_tile_mma_h(
    uint32_t base, int lane, int wy, int wx, float acc[4][4][4])
{
    const uint32_t ba = base, bbb = base + 16384;
    const int g = lane >> 3;
    const int arow = wy*64 + (lane & 7) + ((lane >> 3) & 1) * 8;
    #pragma unroll
    for (int ks = 0; ks < 4; ks++) {
        uint32_t a[4][4];
        const uint32_t abase = (uint32_t)(arow*128 + ks*32 + (lane & 16));
        #pragma unroll
        for (int mt = 0; mt < 4; mt++)
            ldsm4(a[mt], ba + SW(abase + mt*16*128));
        #pragma unroll
        for (int np = 0; np < 2; np++) {
            const int krow = ks*16 + (g & 1)*8 + (lane & 7);
            const int nlg = wx*32 + np*16 + (g >> 1)*8;
            const uint32_t boff = (uint32_t)((nlg >> 6)*8192) + SW((uint32_t)(krow*128 + (nlg & 63)*2));
            uint32_t b[4];
            ldsm4t(b, bbb + boff);
            #pragma unroll
            for (int mt = 0; mt < 4; mt++) {
                mmah(acc[mt][np*2+0], a[mt], b[0], b[1]);
                mmah(acc[mt][np*2+1], a[mt], b[2], b[3]);
            }
        }
    }
}

// shared 3-stage GEMM mainloop
__device__ __forceinline__ void gemm_mainloop(
    uint32_t sb, int tid, int lane, int wy, int wx, int m0, int n0,
    const __half* A, const __half* B, float acc[4][4][4])
{
    gemm_prefetch(sb, 0, tid, m0, n0, 0,  A, DM, B, DM);
    CP_COMMIT();
    gemm_prefetch(sb, 1, tid, m0, n0, 64, A, DM, B, DM);
    CP_COMMIT();
    for (int kt = 0; kt < 16; kt++) {
        if (kt == 15) { CP_WAIT0(); } else { CP_WAIT1(); }
        __syncthreads();
        if (kt < 14) {
            int nb = (kt+2) % 3;
            gemm_prefetch(sb, nb, tid, m0, n0, (kt+2)*64, A, DM, B, DM);
            CP_COMMIT();
        }
        gemm_tile_mma_h(sb + (kt % 3)*GQ_STG, lane, wy, wx, acc);
    }
}

// ---------------------------------------------------------------------------
// QKV projection; epilogue: +bias, RoPE via table (q,k), Q pre-scaled
// ---------------------------------------------------------------------------
__global__ __launch_bounds__(256, 2) void qkv_mma_kernel(
    const float* __restrict__ bq, const float* __restrict__ bk, const float* __restrict__ bv)
{
    extern __shared__ __align__(1024) char smem[];
    const uint32_t sb = smem_u32(smem);
    const int tid = threadIdx.x, wid = tid >> 5, lane = tid & 31;
    const int wy = wid >> 2, wx = wid & 3;
    const int n0 = blockIdx.x * 128;
    const int m0 = blockIdx.y * 128;
    const int z = blockIdx.z;

    const __half* B    = (z==0) ? g_wq : (z==1) ? g_wk : g_wv;
    const float* bias  = (z==0) ? bq   : (z==1) ? bk   : bv;

    float acc[4][4][4];
    #pragma unroll
    for (int a = 0; a < 4; a++)
        #pragma unroll
        for (int b = 0; b < 4; b++)
            #pragma unroll
            for (int c = 0; c < 4; c++) acc[a][b][c] = 0.f;

    gemm_mainloop(sb, tid, lane, wy, wx, m0, n0, g_xh, B, acc);

    __half* dst = (z==0) ? g_q : (z==1) ? g_k : g_v;
    const int gr = lane >> 2, qc = (lane & 3) * 2;
    #pragma unroll
    for (int mt = 0; mt < 4; mt++) {
        #pragma unroll
        for (int h = 0; h < 2; h++) {
            int r = m0 + wy*64 + mt*16 + h*8 + gr;
            int bb = r >> 11;
            int s  = r & 2047;
            #pragma unroll
            for (int nt = 0; nt < 4; nt++) {
                int c = n0 + wx*32 + nt*8 + qc;   // even col
                float v0 = acc[mt][nt][h*2+0] + bias[c];
                float v1 = acc[mt][nt][h*2+1] + bias[c+1];
                float ox = v0, oy = v1;
                if (z < 2) {
                    float2 cssn = g_rope[s*32 + ((c & 63) >> 1)];
                    ox = v0*cssn.x - v1*cssn.y;
                    oy = v0*cssn.y + v1*cssn.x;
                    if (z == 0) { ox *= QSCALE; oy *= QSCALE; }
                }
                int bh = bb*NH + (c >> 6);
                size_t idx = ((size_t)bh*SEQ + s)*DH + (c & 63);
                *(uint32_t*)(dst + idx) = h2pack(ox, oy);
            }
        }
    }
}

// ---------------------------------------------------------------------------
// Fused attention, TWO-PASS, 128-thread CTA, 4 warps x 32 m-rows.
// Pass A: S=QK^T, P=ex2.f16x2(S), rowsum via ones-MMA ONLY (K-only loads).
// Pass B: recompute S, PV accumulate + write ex2f(S)*inv normalized attn
//         (tensor work overlaps the LTS-bound stores).
// ---------------------------------------------------------------------------
#define FA_SQ   0
#define FA_K0   16384
#define FA_K1   24576
#define FA_V0   32768
#define FA_V1   40960
#define FA_SMEM 49152

__device__ __forceinline__ void fa_prefetch_kv(uint32_t sb, int buf, int bh, int k0, int tid)
{
    const __half* kp = g_k + ((size_t)bh*SEQ + k0)*DH;
    const __half* vp = g_v + ((size_t)bh*SEQ + k0)*DH;
    const uint32_t kb = sb + (buf ? FA_K1 : FA_K0);
    const uint32_t vb = sb + (buf ? FA_V1 : FA_V0);
    #pragma unroll
    for (int i = 0; i < 4; i++) {
        int c = tid + i*128;
        int row = c >> 3, part = c & 7;
        uint32_t off = SW((uint32_t)(row*128 + part*16));
        cp16(kb + off, kp + (size_t)row*DH + part*8);
        cp16(vb + off, vp + (size_t)row*DH + part*8);
    }
}

__device__ __forceinline__ void fa_prefetch_k(uint32_t sb, int buf, int bh, int k0, int tid)
{
    const __half* kp = g_k + ((size_t)bh*SEQ + k0)*DH;
    const uint32_t kb = sb + (buf ? FA_K1 : FA_K0);
    #pragma unroll
    for (int i = 0; i < 4; i++) {
        int c = tid + i*128;
        int row = c >> 3, part = c & 7;
        cp16(kb + SW((uint32_t)(row*128 + part*16)), kp + (size_t)row*DH + part*8);
    }
}

__global__ __launch_bounds__(128) void fattn_kernel(float* __restrict__ attn)
{
    extern __shared__ __align__(1024) char smem[];
    const uint32_t sb = smem_u32(smem);
    const int tid = threadIdx.x, wid = tid >> 5, lane = tid & 31;
    const int m0 = blockIdx.x * 128;
    const int bh = blockIdx.y;
    const int g = lane >> 3, gr = lane >> 2, qc = (lane & 3) * 2;

    // load Q tile (128 x 64 fp16, swizzled); 128 threads x 8 iters
    {
        const uint4* qsrc = (const uint4*)(g_q + ((size_t)bh*SEQ + m0)*DH);
        #pragma unroll
        for (int i = 0; i < 8; i++) {
            int c = tid + i*128;
            int row = c >> 3, part = c & 7;
            *(uint4*)(smem + FA_SQ + SW((uint32_t)(row*128 + part*16))) = qsrc[row*8 + part];
        }
    }
    fa_prefetch_k(sb, 0, bh, 0, tid);
    CP_COMMIT();
    __syncthreads();

    // per-warp persistent Q fragments: 2 m-tiles (32 rows) x 64 k
    uint32_t qf[2][4][4];
    #pragma unroll
    for (int mt = 0; mt < 2; mt++) {
        const int arow = wid*32 + mt*16 + (lane & 7) + ((lane >> 3) & 1)*8;
        #pragma unroll
        for (int ks = 0; ks < 4; ks++)
            ldsm4(qf[mt][ks], sb + FA_SQ + SW((uint32_t)(arow*128 + ks*32 + (lane & 16))));
    }

    float ors[2][4] = {{0.f,0.f,0.f,0.f},{0.f,0.f,0.f,0.f}};

    // ---------------- PASS A: rowsum only (K-only loads, no V, no PV) -------
    for (int kt = 0; kt < 32; kt++) {
        CP_WAIT0();
        __syncthreads();
        if (kt < 31) { fa_prefetch_k(sb, (kt+1) & 1, bh, (kt+1)*64, tid); CP_COMMIT(); }

        const uint32_t kb = sb + ((kt & 1) ? FA_K1 : FA_K0);

        #pragma unroll
        for (int nh = 0; nh < 2; nh++) {       // 32-key halves
            float S[2][4][4];
            #pragma unroll
            for (int mt = 0; mt < 2; mt++)
                #pragma unroll
                for (int t = 0; t < 4; t++)
                    #pragma unroll
                    for (int j = 0; j < 4; j++) S[mt][t][j] = 0.f;

            #pragma unroll
            for (int np = 0; np < 2; np++) {
                const int nrow = nh*32 + np*16 + (g >> 1)*8 + (lane & 7);
                #pragma unroll
                for (int ks = 0; ks < 4; ks++) {
                    uint32_t bK[4];
                    ldsm4(bK, kb + SW((uint32_t)(nrow*128 + ks*32 + (g & 1)*16)));
                    #pragma unroll
                    for (int mt = 0; mt < 2; mt++) {
                        mmah(S[mt][np*2+0], qf[mt][ks], bK[0], bK[1]);
                        mmah(S[mt][np*2+1], qf[mt][ks], bK[2], bK[3]);
                    }
                }
            }

            #pragma unroll
            for (int mt = 0; mt < 2; mt++) {
                uint32_t P01[4], P23[4];
                #pragma unroll
                for (int t = 0; t < 4; t++) {
                    P01[t] = ex2_f16x2(cvt_f16x2(S[mt][t][1], S[mt][t][0]));
                    P23[t] = ex2_f16x2(cvt_f16x2(S[mt][t][3], S[mt][t][2]));
                }
                #pragma unroll
                for (int kk = 0; kk < 2; kk++) {
                    uint32_t aP[4];
                    aP[0] = P01[2*kk];   aP[1] = P23[2*kk];
                    aP[2] = P01[2*kk+1]; aP[3] = P23[2*kk+1];
                    mmah(ors[mt], aP, ONESH2, ONESH2);
                }
            }
        }
    }

    float inv[2][2];
    #pragma unroll
    for (int mt = 0; mt < 2; mt++) {
        inv[mt][0] = 1.f / ors[mt][0];
        inv[mt][1] = 1.f / ors[mt][2];
    }

    // all warps done reading pass-A buffers before pass B overwrites K0
    __syncthreads();
    fa_prefetch_kv(sb, 0, bh, 0, tid);
    CP_COMMIT();

    float o[2][8][4];
    #pragma unroll
    for (int mt = 0; mt < 2; mt++)
        #pragma unroll
        for (int t = 0; t < 8; t++)
            #pragma unroll
            for (int j = 0; j < 4; j++) o[mt][t][j] = 0.f;

    float* arow[2][2];
    #pragma unroll
    for (int mt = 0; mt < 2; mt++) {
        const int row0 = m0 + wid*32 + mt*16 + gr;
        arow[mt][0] = attn + ((size_t)bh*SEQ + row0)*SEQ;
        arow[mt][1] = arow[mt][0] + 8*SEQ;
    }

    // ---- PASS B: recompute S, PV accumulate + normalized attn stores -------
    for (int kt = 0; kt < 32; kt++) {
        CP_WAIT0();
        __syncthreads();
        if (kt < 31) { fa_prefetch_kv(sb, (kt+1) & 1, bh, (kt+1)*64, tid); CP_COMMIT(); }

        const uint32_t kb = sb + ((kt & 1) ? FA_K1 : FA_K0);
        const uint32_t vb = sb + ((kt & 1) ? FA_V1 : FA_V0);

        #pragma unroll
        for (int nh = 0; nh < 2; nh++) {
            float S[2][4][4];
            #pragma unroll
            for (int mt = 0; mt < 2; mt++)
                #pragma unroll
                for (int t = 0; t < 4; t++)
                    #pragma unroll
                    for (int j = 0; j < 4; j++) S[mt][t][j] = 0.f;

            #pragma unroll
            for (int np = 0; np < 2; np++) {
                const int nrow = nh*32 + np*16 + (g >> 1)*8 + (lane & 7);
                #pragma unroll
                for (int ks = 0; ks < 4; ks++) {
                    uint32_t bK[4];
                    ldsm4(bK, kb + SW((uint32_t)(nrow*128 + ks*32 + (g & 1)*16)));
                    #pragma unroll
                    for (int mt = 0; mt < 2; mt++) {
                        mmah(S[mt][np*2+0], qf[mt][ks], bK[0], bK[1]);
                        mmah(S[mt][np*2+1], qf[mt][ks], bK[2], bK[3]);
                    }
                }
            }

            // P fragments (fp16) for PV — identical values to pass A
            uint32_t P01[2][4], P23[2][4];
            #pragma unroll
            for (int mt = 0; mt < 2; mt++)
                #pragma unroll
                for (int t = 0; t < 4; t++) {
                    P01[mt][t] = ex2_f16x2(cvt_f16x2(S[mt][t][1], S[mt][t][0]));
                    P23[mt][t] = ex2_f16x2(cvt_f16x2(S[mt][t][3], S[mt][t][2]));
                }

            // normalized attn stores (fire-and-forget, overlap with PV MMAs)
            #pragma unroll
            for (int mt = 0; mt < 2; mt++)
                #pragma unroll
                for (int t = 0; t < 4; t++) {
                    float e0 = ex2f(S[mt][t][0]) * inv[mt][0];
                    float e1 = ex2f(S[mt][t][1]) * inv[mt][0];
                    float e2 = ex2f(S[mt][t][2]) * inv[mt][1];
                    float e3 = ex2f(S[mt][t][3]) * inv[mt][1];
                    int col = kt*64 + nh*32 + t*8 + qc;
                    __stcs((float2*)(arow[mt][0] + col), make_float2(e0, e1));
                    __stcs((float2*)(arow[mt][1] + col), make_float2(e2, e3));
                }

            // PV accumulation
            #pragma unroll
            for (int kk = 0; kk < 2; kk++) {
                uint32_t aP[2][4];
                #pragma unroll
                for (int mt = 0; mt < 2; mt++) {
                    aP[mt][0] = P01[mt][2*kk];   aP[mt][1] = P23[mt][2*kk];
                    aP[mt][2] = P01[mt][2*kk+1]; aP[mt][3] = P23[mt][2*kk+1];
                }
                const int krow = nh*32 + kk*16 + (g & 1)*8 + (lane & 7);
                #pragma unroll
                for (int np = 0; np < 4; np++) {
                    const int ncol = np*16 + (g >> 1)*8;
                    uint32_t bV[4];
                    ldsm4t(bV, vb + SW((uint32_t)(krow*128 + ncol*2)));
                    #pragma unroll
                    for (int mt = 0; mt < 2; mt++) {
                        mmah(o[mt][np*2+0], aP[mt], bV[0], bV[1]);
                        mmah(o[mt][np*2+1], aP[mt], bV[2], bV[3]);
                    }
                }
            }
        }
    }

    // epilogue: normalized head outputs (fp16) into [token][dmodel]
    const int bb = bh >> 4, hh = bh & 15;
    #pragma unroll
    for (int mt = 0; mt < 2; mt++) {
        const int row0 = m0 + wid*32 + mt*16 + gr;
        __half* o0 = g_ohf + ((size_t)bb*SEQ + row0)*DM + hh*64;
        __half* o1 = o0 + 8*DM;
        #pragma unroll
        for (int t = 0; t < 8; t++) {
            *(uint32_t*)(o0 + t*8 + qc) = h2pack(o[mt][t][0]*inv[mt][0], o[mt][t][1]*inv[mt][0]);
            *(uint32_t*)(o1 + t*8 + qc) = h2pack(o[mt][t][2]*inv[mt][1], o[mt][t][3]*inv[mt][1]);
        }
    }
}

// ---------------------------------------------------------------------------
// Output projection: out = oh @ Wo + bo
// ---------------------------------------------------------------------------
__global__ __launch_bounds__(256, 2) void outproj_mma_kernel(
    const float* __restrict__ bo, float* __restrict__ out)
{
    extern __shared__ __align__(1024) char smem[];
    const uint32_t sb = smem_u32(smem);
    const int tid = threadIdx.x, wid = tid >> 5, lane = tid & 31;
    const int wy = wid >> 2, wx = wid & 3;
    const int n0 = blockIdx.x * 128;
    const int m0 = blockIdx.y * 128;

    float acc[4][4][4];
    #pragma unroll
    for (int a = 0; a < 4; a++)
        #pragma unroll
        for (int b = 0; b < 4; b++)
            #pragma unroll
            for (int c = 0; c < 4; c++) acc[a][b][c] = 0.f;

    gemm_mainloop(sb, tid, lane, wy, wx, m0, n0, g_ohf, g_wo, acc);

    const int gr = lane >> 2, qc = (lane & 3) * 2;
    #pragma unroll
    for (int mt = 0; mt < 4; mt++) {
        #pragma unroll
        for (int h = 0; h < 2; h++) {
            int r = m0 + wy*64 + mt*16 + h*8 + gr;
            #pragma unroll
            for (int nt = 0; nt < 4; nt++) {
                int c = n0 + wx*32 + nt*8 + qc;
                float2 oo;
                oo.x = acc[mt][nt][h*2+0] + bo[c];
                oo.y = acc[mt][nt][h*2+1] + bo[c+1];
                *(float2*)(out + (size_t)r*DM + c) = oo;
            }
        }
    }
}

// ---------------------------------------------------------------------------
extern "C" void kernel_launch(void* const* d_in, const int* in_sizes, int n_in,
                              void* d_out, int out_size)
{
    const float* x  = (const float*)d_in[0];
    const float* wq = (const float*)d_in[1];
    const float* bq = (const float*)d_in[2];
    const float* wk = (const float*)d_in[3];
    const float* bk = (const float*)d_in[4];
    const float* wv = (const float*)d_in[5];
    const float* bv = (const float*)d_in[6];
    const float* wo = (const float*)d_in[7];
    const float* bo = (const float*)d_in[8];

    float* out  = (float*)d_out;
    float* attn = out + (size_t)MTOT * DM;   // tuple order: (out, attn)

    static bool init_done = false;
    if (!init_done) {
        cudaFuncSetAttribute(qkv_mma_kernel,     cudaFuncAttributeMaxDynamicSharedMemorySize, GQ_SMEM);
        cudaFuncSetAttribute(outproj_mma_kernel, cudaFuncAttributeMaxDynamicSharedMemorySize, GQ_SMEM);
        cudaFuncSetAttribute(fattn_kernel,       cudaFuncAttributeMaxDynamicSharedMemorySize, FA_SMEM);
        init_done = true;
    }

    {
        __half *xh, *wqh, *wkh, *wvh, *woh;
        cudaGetSymbolAddress((void**)&xh,  g_xh);
        cudaGetSymbolAddress((void**)&wqh, g_wq);
        cudaGetSymbolAddress((void**)&wkh, g_wk);
        cudaGetSymbolAddress((void**)&wvh, g_wv);
        cudaGetSymbolAddress((void**)&woh, g_wo);

        int n4x = MTOT*DM/4, n4w = DM*DM/4;
        rope_table_kernel<<<SEQ*32/256, 256>>>();
        tohalf_kernel<<<(n4x+255)/256, 256>>>((const float4*)x, (uint2*)xh, n4x);
        dim3 gw((n4w+255)/256, 4);
        tohalf4_kernel<<<gw, 256>>>((const float4*)wq, (const float4*)wk,
                                    (const float4*)wv, (const float4*)wo,
                                    (uint2*)wqh, (uint2*)wkh, (uint2*)wvh, (uint2*)woh, n4w);
    }

    dim3 g1(8, 32, 3);
    qkv_mma_kernel<<<g1, 256, GQ_SMEM>>>(bq, bk, bv);

    dim3 g2(16, 32);
    fattn_kernel<<<g2, 128, FA_SMEM>>>(attn);

    dim3 g3(8, 32);
    outproj_mma_kernel<<<g3, 256, GQ_SMEM>>>(bo, out);
}

// round 13
// speedup vs baseline: 1.2624x; 1.0164x over previous
#include <cuda_runtime.h>
#include <cuda_bf16.h>
#include <cuda_fp16.h>
#include <math.h>
#include <stdint.h>

#define BD   2
#define SEQ  2048
#define DM   1024
#define NH   16
#define DH   64
#define MTOT (BD*SEQ)    // 4096
#define BHT  (BD*NH)     // 32

// Q pre-scale: 0.125 * log2(e) so scores arrive in log2 units
#define QSCALE 0.18033688011112042f
#define ONESH2 0x3C003C00u

// ---------------------------------------------------------------------------
// scratch (__device__ globals; allocation-free rule)
// ---------------------------------------------------------------------------
__device__ __half g_q  [BHT*SEQ*DH];     // RoPE'd Q (pre-scaled), fp16 [bh][s][d]
__device__ __half g_k  [BHT*SEQ*DH];     // RoPE'd K
__device__ __half g_v  [BHT*SEQ*DH];     // V
__device__ __half g_xh [MTOT*DM];        // x in fp16
__device__ __half g_wq [DM*DM], g_wk[DM*DM], g_wv[DM*DM], g_wo[DM*DM];
__device__ __half g_ohf[MTOT*DM];        // head outputs [token][dmodel] fp16
__device__ float2 g_rope[SEQ*32];        // (cos, sin) per (s, freq-pair)

// ---------------------------------------------------------------------------
// helpers
// ---------------------------------------------------------------------------
__device__ __forceinline__ uint32_t smem_u32(const void* p) {
    uint32_t a;
    asm("{ .reg .u64 t; cvta.to.shared.u64 t, %1; cvt.u32.u64 %0, t; }" : "=r"(a) : "l"(p));
    return a;
}
__device__ __forceinline__ void ldsm4(uint32_t r[4], uint32_t addr) {
    asm volatile("ldmatrix.sync.aligned.m8n8.x4.shared.b16 {%0,%1,%2,%3}, [%4];"
        : "=r"(r[0]), "=r"(r[1]), "=r"(r[2]), "=r"(r[3]) : "r"(addr));
}
__device__ __forceinline__ void ldsm4t(uint32_t r[4], uint32_t addr) {
    asm volatile("ldmatrix.sync.aligned.m8n8.x4.trans.shared.b16 {%0,%1,%2,%3}, [%4];"
        : "=r"(r[0]), "=r"(r[1]), "=r"(r[2]), "=r"(r[3]) : "r"(addr));
}
__device__ __forceinline__ void mmah(float* c, const uint32_t* a, uint32_t b0, uint32_t b1) {
    asm volatile("mma.sync.aligned.m16n8k16.row.col.f32.f16.f16.f32 "
        "{%0,%1,%2,%3}, {%4,%5,%6,%7}, {%8,%9}, {%0,%1,%2,%3};"
        : "+f"(c[0]), "+f"(c[1]), "+f"(c[2]), "+f"(c[3])
        : "r"(a[0]), "r"(a[1]), "r"(a[2]), "r"(a[3]), "r"(b0), "r"(b1));
}
__device__ __forceinline__ void cp16(uint32_t dst, const void* src) {
    asm volatile("cp.async.cg.shared.global [%0], [%1], 16;" :: "r"(dst), "l"(src));
}
#define CP_COMMIT() asm volatile("cp.async.commit_group;" ::: "memory")
#define CP_WAIT0()  asm volatile("cp.async.wait_group 0;" ::: "memory")
#define CP_WAIT1()  asm volatile("cp.async.wait_group 1;" ::: "memory")
#define SW(o) ((o) ^ (((o) >> 3) & 0x70))

__device__ __forceinline__ uint32_t h2pack(float a, float b) {
    __half2 h = __floats2half2_rn(a, b);
    return *(uint32_t*)&h;
}
__device__ __forceinline__ uint32_t cvt_f16x2(float hi, float lo) {
    uint32_t d; asm("cvt.rn.f16x2.f32 %0, %1, %2;" : "=r"(d) : "f"(hi), "f"(lo)); return d;
}
__device__ __forceinline__ uint32_t ex2_f16x2(uint32_t a) {
    uint32_t d; asm("ex2.approx.f16x2 %0, %1;" : "=r"(d) : "r"(a)); return d;
}
__device__ __forceinline__ float2 h2_to_f2(uint32_t p) {
    __half2 h = *(__half2*)&p;
    return __half22float2(h);   // .x = low half, .y = high half
}

// ---------------------------------------------------------------------------
// prep: fp32 -> fp16  +  RoPE table
// ---------------------------------------------------------------------------
__global__ __launch_bounds__(256) void tohalf_kernel(
    const float4* __restrict__ src, uint2* __restrict__ dst, int n4)
{
    int i = blockIdx.x * 256 + threadIdx.x;
    if (i >= n4) return;
    float4 v = src[i];
    uint2 o;
    o.x = h2pack(v.x, v.y);
    o.y = h2pack(v.z, v.w);
    dst[i] = o;
}

__global__ __launch_bounds__(256) void tohalf4_kernel(
    const float4* __restrict__ s0, const float4* __restrict__ s1,
    const float4* __restrict__ s2, const float4* __restrict__ s3,
    uint2* __restrict__ d0, uint2* __restrict__ d1,
    uint2* __restrict__ d2, uint2* __restrict__ d3, int n4)
{
    int y = blockIdx.y;
    const float4* s = (y==0) ? s0 : (y==1) ? s1 : (y==2) ? s2 : s3;
    uint2* d       = (y==0) ? d0 : (y==1) ? d1 : (y==2) ? d2 : d3;
    int i = blockIdx.x * 256 + threadIdx.x;
    if (i >= n4) return;
    float4 v = s[i];
    uint2 o;
    o.x = h2pack(v.x, v.y);
    o.y = h2pack(v.z, v.w);
    d[i] = o;
}

__global__ __launch_bounds__(256) void rope_table_kernel()
{
    int i = blockIdx.x * 256 + threadIdx.x;   // i < SEQ*32
    int s = i >> 5, j = i & 31;
    float fr = (float)(1.0 / pow(10000.0, (double)(2*j) / 64.0));
    float sn, cs;
    sincosf((float)s * fr, &sn, &cs);
    g_rope[i] = make_float2(cs, sn);
}

// ---------------------------------------------------------------------------
// GEMM core (fp16 HMMA, cp.async 3-stage): C(128x128) = A(128xK) @ B(KxN)
// ---------------------------------------------------------------------------
#define GQ_STG  32768
#define GQ_SMEM (3*GQ_STG)

__device__ __forceinline__ void gemm_prefetch(
    uint32_t sb, int buf, int tid, int m0, int n0, int k0,
    const __half* A, int lda, const __half* B, int ldb)
{
    const uint32_t ab = sb + buf*GQ_STG;
    const uint32_t bb = ab + 16384;
    #pragma unroll
    for (int i = 0; i < 4; i++) {
        int c = tid + i*256;
        int row = c >> 3, part = c & 7;
        cp16(ab + SW((uint32_t)(row*128 + part*16)), A + (size_t)(m0+row)*lda + k0 + part*8);
    }
    #pragma unroll
    for (int i = 0; i < 4; i++) {
        int c = tid + i*256;
        int krow = c >> 4, chunk = c & 15;
        int half_ = chunk >> 3, nl = (chunk & 7) * 8;
        cp16(bb + (uint32_t)(half_*8192) + SW((uint32_t)(krow*128 + nl*2)),
             B + (size_t)(k0+krow)*ldb + n0 + chunk*8);
    }
}

__device__ __forceinline__ void gemm_tile_mma_h(
    uint32_t base, int lane, int wy, int wx, float acc[4][4][4])
{
    const uint32_t ba = base, bbb = base + 16384;
    const int g = lane >> 3;
    const int arow = wy*64 + (lane & 7) + ((lane >> 3) & 1) * 8;
    #pragma unroll
    for (int ks = 0; ks < 4; ks++) {
        uint32_t a[4][4];
        const uint32_t abase = (uint32_t)(arow*128 + ks*32 + (lane & 16));
        #pragma unroll
        for (int mt = 0; mt < 4; mt++)
            ldsm4(a[mt], ba + SW(abase + mt*16*128));
        #pragma unroll
        for (int np = 0; np < 2; np++) {
            const int krow = ks*16 + (g & 1)*8 + (lane & 7);
            const int nlg = wx*32 + np*16 + (g >> 1)*8;
            const uint32_t boff = (uint32_t)((nlg >> 6)*8192) + SW((uint32_t)(krow*128 + (nlg & 63)*2));
            uint32_t b[4];
            ldsm4t(b, bbb + boff);
            #pragma unroll
            for (int mt = 0; mt < 4; mt++) {
                mmah(acc[mt][np*2+0], a[mt], b[0], b[1]);
                mmah(acc[mt][np*2+1], a[mt], b[2], b[3]);
            }
        }
    }
}

__device__ __forceinline__ void gemm_mainloop(
    uint32_t sb, int tid, int lane, int wy, int wx, int m0, int n0,
    const __half* A, const __half* B, float acc[4][4][4])
{
    gemm_prefetch(sb, 0, tid, m0, n0, 0,  A, DM, B, DM);
    CP_COMMIT();
    gemm_prefetch(sb, 1, tid, m0, n0, 64, A, DM, B, DM);
    CP_COMMIT();
    for (int kt = 0; kt < 16; kt++) {
        if (kt == 15) { CP_WAIT0(); } else { CP_WAIT1(); }
        __syncthreads();
        if (kt < 14) {
            int nb = (kt+2) % 3;
            gemm_prefetch(sb, nb, tid, m0, n0, (kt+2)*64, A, DM, B, DM);
            CP_COMMIT();
        }
        gemm_tile_mma_h(sb + (kt % 3)*GQ_STG, lane, wy, wx, acc);
    }
}

// ---------------------------------------------------------------------------
// QKV projection; epilogue: +bias, RoPE via table (q,k), Q pre-scaled
// ---------------------------------------------------------------------------
__global__ __launch_bounds__(256, 2) void qkv_mma_kernel(
    const float* __restrict__ bq, const float* __restrict__ bk, const float* __restrict__ bv)
{
    extern __shared__ __align__(1024) char smem[];
    const uint32_t sb = smem_u32(smem);
    const int tid = threadIdx.x, wid = tid >> 5, lane = tid & 31;
    const int wy = wid >> 2, wx = wid & 3;
    const int n0 = blockIdx.x * 128;
    const int m0 = blockIdx.y * 128;
    const int z = blockIdx.z;

    const __half* B    = (z==0) ? g_wq : (z==1) ? g_wk : g_wv;
    const float* bias  = (z==0) ? bq   : (z==1) ? bk   : bv;

    float acc[4][4][4];
    #pragma unroll
    for (int a = 0; a < 4; a++)
        #pragma unroll
        for (int b = 0; b < 4; b++)
            #pragma unroll
            for (int c = 0; c < 4; c++) acc[a][b][c] = 0.f;

    gemm_mainloop(sb, tid, lane, wy, wx, m0, n0, g_xh, B, acc);

    __half* dst = (z==0) ? g_q : (z==1) ? g_k : g_v;
    const int gr = lane >> 2, qc = (lane & 3) * 2;
    #pragma unroll
    for (int mt = 0; mt < 4; mt++) {
        #pragma unroll
        for (int h = 0; h < 2; h++) {
            int r = m0 + wy*64 + mt*16 + h*8 + gr;
            int bb = r >> 11;
            int s  = r & 2047;
            #pragma unroll
            for (int nt = 0; nt < 4; nt++) {
                int c = n0 + wx*32 + nt*8 + qc;   // even col
                float v0 = acc[mt][nt][h*2+0] + bias[c];
                float v1 = acc[mt][nt][h*2+1] + bias[c+1];
                float ox = v0, oy = v1;
                if (z < 2) {
                    float2 cssn = g_rope[s*32 + ((c & 63) >> 1)];
                    ox = v0*cssn.x - v1*cssn.y;
                    oy = v0*cssn.y + v1*cssn.x;
                    if (z == 0) { ox *= QSCALE; oy *= QSCALE; }
                }
                int bh = bb*NH + (c >> 6);
                size_t idx = ((size_t)bh*SEQ + s)*DH + (c & 63);
                *(uint32_t*)(dst + idx) = h2pack(ox, oy);
            }
        }
    }
}

// ---------------------------------------------------------------------------
// Fused attention, TWO-PASS, 128-thread CTA, 4 warps x 32 m-rows.
// Pass A: S=QK^T, P=ex2.f16x2(S), rowsum via ones-MMA (K-only loads).
// Pass B: recompute S, P=ex2.f16x2(S); attn values derived from the SAME
//         fp16 P fragments ((float)P * inv) -> no f32 MUFU; PV accumulate.
// ---------------------------------------------------------------------------
#define FA_SQ   0
#define FA_K0   16384
#define FA_K1   24576
#define FA_V0   32768
#define FA_V1   40960
#define FA_SMEM 49152

__device__ __forceinline__ void fa_prefetch_kv(uint32_t sb, int buf, int bh, int k0, int tid)
{
    const __half* kp = g_k + ((size_t)bh*SEQ + k0)*DH;
    const __half* vp = g_v + ((size_t)bh*SEQ + k0)*DH;
    const uint32_t kb = sb + (buf ? FA_K1 : FA_K0);
    const uint32_t vb = sb + (buf ? FA_V1 : FA_V0);
    #pragma unroll
    for (int i = 0; i < 4; i++) {
        int c = tid + i*128;
        int row = c >> 3, part = c & 7;
        uint32_t off = SW((uint32_t)(row*128 + part*16));
        cp16(kb + off, kp + (size_t)row*DH + part*8);
        cp16(vb + off, vp + (size_t)row*DH + part*8);
    }
}

__device__ __forceinline__ void fa_prefetch_k(uint32_t sb, int buf, int bh, int k0, int tid)
{
    const __half* kp = g_k + ((size_t)bh*SEQ + k0)*DH;
    const uint32_t kb = sb + (buf ? FA_K1 : FA_K0);
    #pragma unroll
    for (int i = 0; i < 4; i++) {
        int c = tid + i*128;
        int row = c >> 3, part = c & 7;
        cp16(kb + SW((uint32_t)(row*128 + part*16)), kp + (size_t)row*DH + part*8);
    }
}

__global__ __launch_bounds__(128) void fattn_kernel(float* __restrict__ attn)
{
    extern __shared__ __align__(1024) char smem[];
    const uint32_t sb = smem_u32(smem);
    const int tid = threadIdx.x, wid = tid >> 5, lane = tid & 31;
    const int m0 = blockIdx.x * 128;
    const int bh = blockIdx.y;
    const int g = lane >> 3, gr = lane >> 2, qc = (lane & 3) * 2;

    // load Q tile (128 x 64 fp16, swizzled)
    {
        const uint4* qsrc = (const uint4*)(g_q + ((size_t)bh*SEQ + m0)*DH);
        #pragma unroll
        for (int i = 0; i < 8; i++) {
            int c = tid + i*128;
            int row = c >> 3, part = c & 7;
            *(uint4*)(smem + FA_SQ + SW((uint32_t)(row*128 + part*16))) = qsrc[row*8 + part];
        }
    }
    fa_prefetch_k(sb, 0, bh, 0, tid);
    CP_COMMIT();
    __syncthreads();

    // per-warp persistent Q fragments: 2 m-tiles (32 rows) x 64 k
    uint32_t qf[2][4][4];
    #pragma unroll
    for (int mt = 0; mt < 2; mt++) {
        const int arow = wid*32 + mt*16 + (lane & 7) + ((lane >> 3) & 1)*8;
        #pragma unroll
        for (int ks = 0; ks < 4; ks++)
            ldsm4(qf[mt][ks], sb + FA_SQ + SW((uint32_t)(arow*128 + ks*32 + (lane & 16))));
    }

    float ors[2][4] = {{0.f,0.f,0.f,0.f},{0.f,0.f,0.f,0.f}};

    // ---------------- PASS A: rowsum only (K-only loads) --------------------
    for (int kt = 0; kt < 32; kt++) {
        CP_WAIT0();
        __syncthreads();
        if (kt < 31) { fa_prefetch_k(sb, (kt+1) & 1, bh, (kt+1)*64, tid); CP_COMMIT(); }

        const uint32_t kb = sb + ((kt & 1) ? FA_K1 : FA_K0);

        #pragma unroll
        for (int nh = 0; nh < 2; nh++) {       // 32-key halves
            float S[2][4][4];
            #pragma unroll
            for (int mt = 0; mt < 2; mt++)
                #pragma unroll
                for (int t = 0; t < 4; t++)
                    #pragma unroll
                    for (int j = 0; j < 4; j++) S[mt][t][j] = 0.f;

            #pragma unroll
            for (int np = 0; np < 2; np++) {
                const int nrow = nh*32 + np*16 + (g >> 1)*8 + (lane & 7);
                #pragma unroll
                for (int ks = 0; ks < 4; ks++) {
                    uint32_t bK[4];
                    ldsm4(bK, kb + SW((uint32_t)(nrow*128 + ks*32 + (g & 1)*16)));
                    #pragma unroll
                    for (int mt = 0; mt < 2; mt++) {
                        mmah(S[mt][np*2+0], qf[mt][ks], bK[0], bK[1]);
                        mmah(S[mt][np*2+1], qf[mt][ks], bK[2], bK[3]);
                    }
                }
            }

            #pragma unroll
            for (int mt = 0; mt < 2; mt++) {
                uint32_t P01[4], P23[4];
                #pragma unroll
                for (int t = 0; t < 4; t++) {
                    P01[t] = ex2_f16x2(cvt_f16x2(S[mt][t][1], S[mt][t][0]));
                    P23[t] = ex2_f16x2(cvt_f16x2(S[mt][t][3], S[mt][t][2]));
                }
                #pragma unroll
                for (int kk = 0; kk < 2; kk++) {
                    uint32_t aP[4];
                    aP[0] = P01[2*kk];   aP[1] = P23[2*kk];
                    aP[2] = P01[2*kk+1]; aP[3] = P23[2*kk+1];
                    mmah(ors[mt], aP, ONESH2, ONESH2);
                }
            }
        }
    }

    float inv[2][2];
    #pragma unroll
    for (int mt = 0; mt < 2; mt++) {
        inv[mt][0] = 1.f / ors[mt][0];
        inv[mt][1] = 1.f / ors[mt][2];
    }

    // all warps done reading pass-A buffers before pass B overwrites K0
    __syncthreads();
    fa_prefetch_kv(sb, 0, bh, 0, tid);
    CP_COMMIT();

    float o[2][8][4];
    #pragma unroll
    for (int mt = 0; mt < 2; mt++)
        #pragma unroll
        for (int t = 0; t < 8; t++)
            #pragma unroll
            for (int j = 0; j < 4; j++) o[mt][t][j] = 0.f;

    float* arow[2][2];
    #pragma unroll
    for (int mt = 0; mt < 2; mt++) {
        const int row0 = m0 + wid*32 + mt*16 + gr;
        arow[mt][0] = attn + ((size_t)bh*SEQ + row0)*SEQ;
        arow[mt][1] = arow[mt][0] + 8*SEQ;
    }

    // ---- PASS B: recompute S; attn from fp16 P (no f32 MUFU); PV -----------
    for (int kt = 0; kt < 32; kt++) {
        CP_WAIT0();
        __syncthreads();
        if (kt < 31) { fa_prefetch_kv(sb, (kt+1) & 1, bh, (kt+1)*64, tid); CP_COMMIT(); }

        const uint32_t kb = sb + ((kt & 1) ? FA_K1 : FA_K0);
        const uint32_t vb = sb + ((kt & 1) ? FA_V1 : FA_V0);

        #pragma unroll
        for (int nh = 0; nh < 2; nh++) {
            float S[2][4][4];
            #pragma unroll
            for (int mt = 0; mt < 2; mt++)
                #pragma unroll
                for (int t = 0; t < 4; t++)
                    #pragma unroll
                    for (int j = 0; j < 4; j++) S[mt][t][j] = 0.f;

            #pragma unroll
            for (int np = 0; np < 2; np++) {
                const int nrow = nh*32 + np*16 + (g >> 1)*8 + (lane & 7);
                #pragma unroll
                for (int ks = 0; ks < 4; ks++) {
                    uint32_t bK[4];
                    ldsm4(bK, kb + SW((uint32_t)(nrow*128 + ks*32 + (g & 1)*16)));
                    #pragma unroll
                    for (int mt = 0; mt < 2; mt++) {
                        mmah(S[mt][np*2+0], qf[mt][ks], bK[0], bK[1]);
                        mmah(S[mt][np*2+1], qf[mt][ks], bK[2], bK[3]);
                    }
                }
            }

            // P fragments (fp16) — same values as pass A
            uint32_t P01[2][4], P23[2][4];
            #pragma unroll
            for (int mt = 0; mt < 2; mt++)
                #pragma unroll
                for (int t = 0; t < 4; t++) {
                    P01[mt][t] = ex2_f16x2(cvt_f16x2(S[mt][t][1], S[mt][t][0]));
                    P23[mt][t] = ex2_f16x2(cvt_f16x2(S[mt][t][3], S[mt][t][2]));
                }

            // attn stores derived from fp16 P (H2F + FMUL; no MUFU)
            #pragma unroll
            for (int mt = 0; mt < 2; mt++)
                #pragma unroll
                for (int t = 0; t < 4; t++) {
                    float2 f01 = h2_to_f2(P01[mt][t]);   // .x=e(S0), .y=e(S1)
                    float2 f23 = h2_to_f2(P23[mt][t]);   // .x=e(S2), .y=e(S3)
                    int col = kt*64 + nh*32 + t*8 + qc;
                    __stcs((float2*)(arow[mt][0] + col),
                           make_float2(f01.x*inv[mt][0], f01.y*inv[mt][0]));
                    __stcs((float2*)(arow[mt][1] + col),
                           make_float2(f23.x*inv[mt][1], f23.y*inv[mt][1]));
                }

            // PV accumulation
            #pragma unroll
            for (int kk = 0; kk < 2; kk++) {
                uint32_t aP[2][4];
                #pragma unroll
                for (int mt = 0; mt < 2; mt++) {
                    aP[mt][0] = P01[mt][2*kk];   aP[mt][1] = P23[mt][2*kk];
                    aP[mt][2] = P01[mt][2*kk+1]; aP[mt][3] = P23[mt][2*kk+1];
                }
                const int krow = nh*32 + kk*16 + (g & 1)*8 + (lane & 7);
                #pragma unroll
                for (int np = 0; np < 4; np++) {
                    const int ncol = np*16 + (g >> 1)*8;
                    uint32_t bV[4];
                    ldsm4t(bV, vb + SW((uint32_t)(krow*128 + ncol*2)));
                    #pragma unroll
                    for (int mt = 0; mt < 2; mt++) {
                        mmah(o[mt][np*2+0], aP[mt], bV[0], bV[1]);
                        mmah(o[mt][np*2+1], aP[mt], bV[2], bV[3]);
                    }
                }
            }
        }
    }

    // epilogue: normalized head outputs (fp16) into [token][dmodel]
    const int bb = bh >> 4, hh = bh & 15;
    #pragma unroll
    for (int mt = 0; mt < 2; mt++) {
        const int row0 = m0 + wid*32 + mt*16 + gr;
        __half* o0 = g_ohf + ((size_t)bb*SEQ + row0)*DM + hh*64;
        __half* o1 = o0 + 8*DM;
        #pragma unroll
        for (int t = 0; t < 8; t++) {
            *(uint32_t*)(o0 + t*8 + qc) = h2pack(o[mt][t][0]*inv[mt][0], o[mt][t][1]*inv[mt][0]);
            *(uint32_t*)(o1 + t*8 + qc) = h2pack(o[mt][t][2]*inv[mt][1], o[mt][t][3]*inv[mt][1]);
        }
    }
}

// ---------------------------------------------------------------------------
// Output projection: out = oh @ Wo + bo
// ---------------------------------------------------------------------------
__global__ __launch_bounds__(256, 2) void outproj_mma_kernel(
    const float* __restrict__ bo, float* __restrict__ out)
{
    extern __shared__ __align__(1024) char smem[];
    const uint32_t sb = smem_u32(smem);
    const int tid = threadIdx.x, wid = tid >> 5, lane = tid & 31;
    const int wy = wid >> 2, wx = wid & 3;
    const int n0 = blockIdx.x * 128;
    const int m0 = blockIdx.y * 128;

    float acc[4][4][4];
    #pragma unroll
    for (int a = 0; a < 4; a++)
        #pragma unroll
        for (int b = 0; b < 4; b++)
            #pragma unroll
            for (int c = 0; c < 4; c++) acc[a][b][c] = 0.f;

    gemm_mainloop(sb, tid, lane, wy, wx, m0, n0, g_ohf, g_wo, acc);

    const int gr = lane >> 2, qc = (lane & 3) * 2;
    #pragma unroll
    for (int mt = 0; mt < 4; mt++) {
        #pragma unroll
        for (int h = 0; h < 2; h++) {
            int r = m0 + wy*64 + mt*16 + h*8 + gr;
            #pragma unroll
            for (int nt = 0; nt < 4; nt++) {
                int c = n0 + wx*32 + nt*8 + qc;
                float2 oo;
                oo.x = acc[mt][nt][h*2+0] + bo[c];
                oo.y = acc[mt][nt][h*2+1] + bo[c+1];
                *(float2*)(out + (size_t)r*DM + c) = oo;
            }
        }
    }
}

// ---------------------------------------------------------------------------
extern "C" void kernel_launch(void* const* d_in, const int* in_sizes, int n_in,
                              void* d_out, int out_size)
{
    const float* x  = (const float*)d_in[0];
    const float* wq = (const float*)d_in[1];
    const float* bq = (const float*)d_in[2];
    const float* wk = (const float*)d_in[3];
    const float* bk = (const float*)d_in[4];
    const float* wv = (const float*)d_in[5];
    const float* bv = (const float*)d_in[6];
    const float* wo = (const float*)d_in[7];
    const float* bo = (const float*)d_in[8];

    float* out  = (float*)d_out;
    float* attn = out + (size_t)MTOT * DM;   // tuple order: (out, attn)

    static bool init_done = false;
    if (!init_done) {
        cudaFuncSetAttribute(qkv_mma_kernel,     cudaFuncAttributeMaxDynamicSharedMemorySize, GQ_SMEM);
        cudaFuncSetAttribute(outproj_mma_kernel, cudaFuncAttributeMaxDynamicSharedMemorySize, GQ_SMEM);
        cudaFuncSetAttribute(fattn_kernel,       cudaFuncAttributeMaxDynamicSharedMemorySize, FA_SMEM);
        init_done = true;
    }

    {
        __half *xh, *wqh, *wkh, *wvh, *woh;
        cudaGetSymbolAddress((void**)&xh,  g_xh);
        cudaGetSymbolAddress((void**)&wqh, g_wq);
        cudaGetSymbolAddress((void**)&wkh, g_wk);
        cudaGetSymbolAddress((void**)&wvh, g_wv);
        cudaGetSymbolAddress((void**)&woh, g_wo);

        int n4x = MTOT*DM/4, n4w = DM*DM/4;
        rope_table_kernel<<<SEQ*32/256, 256>>>();
        tohalf_kernel<<<(n4x+255)/256, 256>>>((const float4*)x, (uint2*)xh, n4x);
        dim3 gw((n4w+255)/256, 4);
        tohalf4_kernel<<<gw, 256>>>((const float4*)wq, (const float4*)wk,
                                    (const float4*)wv, (const float4*)wo,
                                    (uint2*)wqh, (uint2*)wkh, (uint2*)wvh, (uint2*)woh, n4w);
    }

    dim3 g1(8, 32, 3);
    qkv_mma_kernel<<<g1, 256, GQ_SMEM>>>(bq, bk, bv);

    dim3 g2(16, 32);
    fattn_kernel<<<g2, 128, FA_SMEM>>>(attn);

    dim3 g3(8, 32);
    outproj_mma_kernel<<<g3, 256, GQ_SMEM>>>(bo, out);
}